// round 14
// baseline (speedup 1.0000x reference)
#include <cuda_runtime.h>
#include <cuda_bf16.h>
#include <cuda_fp16.h>
#include <math.h>
#include <stdint.h>

// ---------------------------------------------------------------------------
// Problem constants
// ---------------------------------------------------------------------------
#define NH    8
#define DH    32
#define HID   256
#define INC   768
#define OUTC  128
#define NTOT  270000
#define NRMAX 200000
#define EMAX  200000
#define LAY   2

// ---------------------------------------------------------------------------
// Scratch (static device globals; allocation APIs forbidden). ~1.53 GB.
// ---------------------------------------------------------------------------
__device__ float g_x  [(size_t)NTOT * HID];   // used as bf16 hi activations
__device__ float g_x2 [(size_t)NTOT * HID];   // used as bf16 lo activations
__device__ float g_Q  [(size_t)NTOT * HID];   // used as __half
__device__ float g_o  [(size_t)NTOT * HID];   // fp32 attention accum
__device__ float g_kr [(size_t)NRMAX * HID];  // used as __half
__device__ float g_vr [(size_t)NRMAX * HID];
__device__ float g_lg [(size_t)EMAX * NH];
__device__ float g_dn [(size_t)NRMAX * NH];
// relation-folded K/V weights (fp32, [K][N])
__device__ float g_we [(size_t)2 * LAY * 3 * HID * HID];
__device__ float g_be [(size_t)2 * LAY * 3 * HID];
// all GEMM weights, transposed to [N][K], split into bf16 hi/lo
#define WB_W1 0
#define WB_WQ (WB_W1 + 256*768)
#define WB_WE (WB_WQ + 6*256*256)
#define WB_WA (WB_WE + 12*256*256)
#define WB_W2 (WB_WA + 6*256*256)
#define WB_TOT (WB_W2 + 128*256)
__device__ __nv_bfloat16 g_bh[WB_TOT];
__device__ __nv_bfloat16 g_bl[WB_TOT];

// ---------------------------------------------------------------------------
// Helpers
// ---------------------------------------------------------------------------
__device__ __forceinline__ uint32_t smem_u32(const void* p) {
    uint32_t a;
    asm("{ .reg .u64 t; cvta.to.shared.u64 t, %1; cvt.u32.u64 %0, t; }"
        : "=r"(a) : "l"(p));
    return a;
}
__device__ __forceinline__ float geluf(float v) {
    return 0.5f * v * (1.0f + erff(v * 0.70710678118654752f));
}

__device__ __forceinline__ void mma_bf16(float* c, const uint32_t* a,
                                         const uint32_t* b) {
    asm volatile(
        "mma.sync.aligned.m16n8k16.row.col.f32.bf16.bf16.f32 "
        "{%0,%1,%2,%3}, {%4,%5,%6,%7}, {%8,%9}, {%0,%1,%2,%3};\n"
        : "+f"(c[0]), "+f"(c[1]), "+f"(c[2]), "+f"(c[3])
        : "r"(a[0]), "r"(a[1]), "r"(a[2]), "r"(a[3]), "r"(b[0]), "r"(b[1]));
}
__device__ __forceinline__ void ldm_x4(uint32_t* r, uint32_t addr) {
    asm volatile("ldmatrix.sync.aligned.m8n8.x4.shared.b16 {%0,%1,%2,%3}, [%4];"
        : "=r"(r[0]), "=r"(r[1]), "=r"(r[2]), "=r"(r[3]) : "r"(addr));
}
__device__ __forceinline__ void ldm_x2(uint32_t* r, uint32_t addr) {
    asm volatile("ldmatrix.sync.aligned.m8n8.x2.shared.b16 {%0,%1}, [%2];"
        : "=r"(r[0]), "=r"(r[1]) : "r"(addr));
}
#define CP_ASYNC16P(dst, src, p) \
    asm volatile("cp.async.cg.shared.global [%0], [%1], 16, %2;" \
                 :: "r"(dst), "l"(src), "r"(p))
#define CP_COMMIT() asm volatile("cp.async.commit_group;" ::: "memory")
#define CP_WAIT1()  asm volatile("cp.async.wait_group 1;" ::: "memory")
#define CP_WAIT0()  asm volatile("cp.async.wait_group 0;" ::: "memory")

// ---------------------------------------------------------------------------
// Fold relation matrices into K/V projection weights (verified R3-R13)
// ---------------------------------------------------------------------------
__global__ __launch_bounds__(256)
void wtrans_k(const float* __restrict__ Wk, const float* __restrict__ bk,
              const float* __restrict__ Wv, const float* __restrict__ bv,
              const float* __restrict__ a_rel, const float* __restrict__ m_rel,
              float* __restrict__ We, float* __restrict__ be)
{
    const int styp[3] = { 1, 0, 2 };
    int idx = blockIdx.x;
    int h   = idx & 7;
    int e   = (idx >> 3) % 3;
    int l   = ((idx >> 3) / 3) % LAY;
    int kv  = idx / (8 * 3 * LAY);
    int s   = styp[e];

    const float* W = (kv == 0 ? Wk : Wv) + (size_t)(l * 3 + s) * HID * HID;
    const float* b = (kv == 0 ? bk : bv) + (size_t)(l * 3 + s) * HID;
    const float* A = (kv == 0 ? a_rel : m_rel)
                   + ((size_t)(l * 3 + e) * NH + h) * DH * DH;
    float* Wo = We + (size_t)((kv * LAY + l) * 3 + e) * HID * HID;
    float* bo = be + (size_t)((kv * LAY + l) * 3 + e) * HID;

    __shared__ float sA[DH][DH];
    if (threadIdx.x < DH * DH / 2) {
        int d = threadIdx.x >> 4, c = (threadIdx.x & 15) * 2;
        sA[d][c]     = A[d * DH + c];
        sA[d][c + 1] = A[d * DH + c + 1];
        sA[d + 16][c]     = A[(d + 16) * DH + c];
        sA[d + 16][c + 1] = A[(d + 16) * DH + c + 1];
    }
    __syncthreads();

    int i = threadIdx.x;
    float w[DH];
#pragma unroll
    for (int d = 0; d < DH; d++) w[d] = W[(size_t)i * HID + h * DH + d];
#pragma unroll 4
    for (int c = 0; c < DH; c++) {
        float acc = 0.0f;
#pragma unroll
        for (int d = 0; d < DH; d++) acc += w[d] * sA[d][c];
        Wo[(size_t)i * HID + h * DH + c] = acc;
    }
    if (i < DH) {
        float acc = 0.0f;
#pragma unroll
        for (int d = 0; d < DH; d++) acc += b[h * DH + d] * sA[d][i];
        bo[h * DH + i] = acc;
    }
}

// ---------------------------------------------------------------------------
// Transpose + split fp32 weight [K][N] -> bf16 hi/lo [N][K] (W1 only)
// ---------------------------------------------------------------------------
__global__ __launch_bounds__(256)
void wsplit_k(const float* __restrict__ src, __nv_bfloat16* __restrict__ hi,
              __nv_bfloat16* __restrict__ lo, int K, int N)
{
    int i = blockIdx.x * 256 + threadIdx.x;
    if (i >= K * N) return;
    int n = i / K, k = i - n * K;
    float w = src[(size_t)k * N + n];
    __nv_bfloat16 h = __float2bfloat16(w);
    hi[i] = h;
    lo[i] = __float2bfloat16(w - __bfloat162float(h));
}

// ---------------------------------------------------------------------------
// Batched transpose+split for all K=256 weights: Wq(6) We(12) Wa(6) W2(1).
// ---------------------------------------------------------------------------
__global__ __launch_bounds__(256)
void wsplit_all(const float* __restrict__ Wq, const float* __restrict__ We,
                const float* __restrict__ Wa, const float* __restrict__ W2,
                __nv_bfloat16* __restrict__ bh, __nv_bfloat16* __restrict__ bl)
{
    int bid = blockIdx.x;
    const float* src;
    size_t off;
    int N, inner;
    if (bid < 6144) {
        int seg = bid >> 8;
        inner = ((bid & 255) << 8) | threadIdx.x;
        N = 256;
        if (seg < 6)       { src = Wq + (size_t)seg * 65536;        off = WB_WQ + (size_t)seg * 65536; }
        else if (seg < 18) { src = We + (size_t)(seg - 6) * 65536;  off = WB_WE + (size_t)(seg - 6) * 65536; }
        else               { src = Wa + (size_t)(seg - 18) * 65536; off = WB_WA + (size_t)(seg - 18) * 65536; }
    } else {
        inner = ((bid - 6144) << 8) | threadIdx.x;
        N = 128; src = W2; off = WB_W2;
    }
    int n = inner >> 8;
    int k = inner & 255;
    float w = src[(size_t)k * N + n];
    __nv_bfloat16 h = __float2bfloat16(w);
    bh[off + inner] = h;
    bl[off + inner] = __float2bfloat16(w - __bfloat162float(h));
}

#define LDS 40   // smem row stride in halves (80B: conflict-free ldmatrix)

// ---------------------------------------------------------------------------
// Fully-async convert GEMM: fp32 A staged raw via cp.async (double-buffered,
// stride-36 fp32 rows = conflict-free), converted smem->smem to a single
// Abf hi/lo pair, then the proven ldmatrix/MMA block. B bf16 pair staged
// via cp.async alongside. 3 syncs/chunk; exact wait-group accounting.
// outmode: 0 = fp32 C, 1 = __half C, 2 = bf16 hi/lo pair (Ch, Cl)
// epi=2 reads skip input from bf16 pair (Xh, Xl).
// ---------------------------------------------------------------------------
#define CSTG_BYTES 38912              // A32 18432 + Bh 10240 + Bl 10240
#define CABF_OFF   (2 * CSTG_BYTES)   // 77824
#define DSMEM_C    (CABF_OFF + 2 * 10240)  // 98304

__global__ __launch_bounds__(256)
void gemm_cvt(const float* __restrict__ A,
              const __nv_bfloat16* __restrict__ Bh,
              const __nv_bfloat16* __restrict__ Bl,
              const float* __restrict__ bias,
              const __nv_bfloat16* __restrict__ Xh,
              const __nv_bfloat16* __restrict__ Xl,
              const float* __restrict__ skipp, float* __restrict__ C,
              __nv_bfloat16* __restrict__ Ch, __nv_bfloat16* __restrict__ Cl,
              int M, int N, int K, int actA, int epi, int outmode)
{
    extern __shared__ __align__(16) char smc[];
    const uint32_t smb = smem_u32(smc);

    const int tid  = threadIdx.x;
    const int wid  = tid >> 5;
    const int lane = tid & 31;
    const int wm   = wid >> 2;
    const int wn   = wid & 3;
    const int row0 = blockIdx.y * 128;
    const int col0 = blockIdx.x * 128;

    const int a_r = (lane & 7) + ((lane >> 3) & 1) * 8;
    const int a_c = ((lane >> 4) & 1) * 8;
    const int b_r = (lane & 7);
    const int b_c = ((lane >> 3) & 1) * 8;
    const uint32_t aoff = (uint32_t)((wm * 64 + a_r) * LDS + a_c) * 2;
    const uint32_t boff = (uint32_t)((wn * 32 + b_r) * LDS + b_c) * 2;

    // convert-phase addressing: thread -> (row = tid>>1, half = tid&1)
    const uint32_t a32r = (uint32_t)((tid >> 1) * 144 + (tid & 1) * 64);
    const uint32_t sto  = (uint32_t)((tid >> 1) * LDS + (tid & 1) * 16);

    const uint32_t uAh = smb + CABF_OFF;
    const uint32_t uAl = uAh + 10240;
    __nv_bfloat16* pAbfH = (__nv_bfloat16*)(smc + CABF_OFF);
    __nv_bfloat16* pAbfL = (__nv_bfloat16*)(smc + CABF_OFF + 10240);

    float acc[4][4][4];
#pragma unroll
    for (int i = 0; i < 4; i++)
#pragma unroll
        for (int j = 0; j < 4; j++)
#pragma unroll
            for (int r = 0; r < 4; r++) acc[i][j][r] = 0.0f;

    const int NC = K / 32;

    auto issue = [&](int chunk) {
        const int stg = chunk & 1;
        const uint32_t sb = smb + stg * CSTG_BYTES;
        const int kb = chunk * 32;
#pragma unroll
        for (int i = 0; i < 4; i++) {
            int cid = tid + i * 256;
            int row = cid >> 3, seg = cid & 7;
            uint32_t dst = sb + (uint32_t)(row * 144 + seg * 16);
            int ga = row0 + row;
            uint32_t pa = (ga < M) ? 16u : 0u;
            CP_ASYNC16P(dst, A + (size_t)ga * K + kb + seg * 4, pa);
        }
#pragma unroll
        for (int i = 0; i < 2; i++) {
            int cid = tid + i * 256;
            int row = cid >> 2, seg = cid & 3;
            uint32_t dst = sb + 18432 + (uint32_t)(row * LDS * 2 + seg * 16);
            CP_ASYNC16P(dst,         Bh + (size_t)(col0 + row) * K + kb + seg * 8, 16u);
            CP_ASYNC16P(dst + 10240, Bl + (size_t)(col0 + row) * K + kb + seg * 8, 16u);
        }
        CP_COMMIT();
    };

    issue(0);
    if (NC > 1) issue(1);

    for (int c = 0; c < NC; c++) {
        const int stg = c & 1;
        if (c >= NC - 1) CP_WAIT0(); else CP_WAIT1();
        __syncthreads();   // stage c landed; mma(c-1) finished by all warps

        // ---- convert staged fp32 A -> Abf hi/lo pair ----
        const char* a32 = smc + stg * CSTG_BYTES;
        float4 f0 = *(const float4*)(a32 + a32r);
        float4 f1 = *(const float4*)(a32 + a32r + 16);
        float4 f2 = *(const float4*)(a32 + a32r + 32);
        float4 f3 = *(const float4*)(a32 + a32r + 48);
        if (actA) {
            f0.x = geluf(f0.x); f0.y = geluf(f0.y); f0.z = geluf(f0.z); f0.w = geluf(f0.w);
            f1.x = geluf(f1.x); f1.y = geluf(f1.y); f1.z = geluf(f1.z); f1.w = geluf(f1.w);
            f2.x = geluf(f2.x); f2.y = geluf(f2.y); f2.z = geluf(f2.z); f2.w = geluf(f2.w);
            f3.x = geluf(f3.x); f3.y = geluf(f3.y); f3.z = geluf(f3.z); f3.w = geluf(f3.w);
        }
        __nv_bfloat162 h0 = __floats2bfloat162_rn(f0.x, f0.y);
        __nv_bfloat162 h1 = __floats2bfloat162_rn(f0.z, f0.w);
        __nv_bfloat162 h2 = __floats2bfloat162_rn(f1.x, f1.y);
        __nv_bfloat162 h3 = __floats2bfloat162_rn(f1.z, f1.w);
        __nv_bfloat162 h4 = __floats2bfloat162_rn(f2.x, f2.y);
        __nv_bfloat162 h5 = __floats2bfloat162_rn(f2.z, f2.w);
        __nv_bfloat162 h6 = __floats2bfloat162_rn(f3.x, f3.y);
        __nv_bfloat162 h7 = __floats2bfloat162_rn(f3.z, f3.w);
        __nv_bfloat162 l0 = __floats2bfloat162_rn(f0.x - __bfloat162float(h0.x), f0.y - __bfloat162float(h0.y));
        __nv_bfloat162 l1 = __floats2bfloat162_rn(f0.z - __bfloat162float(h1.x), f0.w - __bfloat162float(h1.y));
        __nv_bfloat162 l2 = __floats2bfloat162_rn(f1.x - __bfloat162float(h2.x), f1.y - __bfloat162float(h2.y));
        __nv_bfloat162 l3 = __floats2bfloat162_rn(f1.z - __bfloat162float(h3.x), f1.w - __bfloat162float(h3.y));
        __nv_bfloat162 l4 = __floats2bfloat162_rn(f2.x - __bfloat162float(h4.x), f2.y - __bfloat162float(h4.y));
        __nv_bfloat162 l5 = __floats2bfloat162_rn(f2.z - __bfloat162float(h5.x), f2.w - __bfloat162float(h5.y));
        __nv_bfloat162 l6 = __floats2bfloat162_rn(f3.x - __bfloat162float(h6.x), f3.y - __bfloat162float(h6.y));
        __nv_bfloat162 l7 = __floats2bfloat162_rn(f3.z - __bfloat162float(h7.x), f3.w - __bfloat162float(h7.y));
        *(uint4*)(pAbfH + sto)     = make_uint4(*(uint32_t*)&h0, *(uint32_t*)&h1, *(uint32_t*)&h2, *(uint32_t*)&h3);
        *(uint4*)(pAbfH + sto + 8) = make_uint4(*(uint32_t*)&h4, *(uint32_t*)&h5, *(uint32_t*)&h6, *(uint32_t*)&h7);
        *(uint4*)(pAbfL + sto)     = make_uint4(*(uint32_t*)&l0, *(uint32_t*)&l1, *(uint32_t*)&l2, *(uint32_t*)&l3);
        *(uint4*)(pAbfL + sto + 8) = make_uint4(*(uint32_t*)&l4, *(uint32_t*)&l5, *(uint32_t*)&l6, *(uint32_t*)&l7);
        __syncthreads();   // Abf pair visible

        // ---- MMA block (proven) ----
        const uint32_t uBh = smb + stg * CSTG_BYTES + 18432;
        const uint32_t uBl = uBh + 10240;
#pragma unroll
        for (int ks = 0; ks < 2; ks++) {
            const uint32_t kof = (uint32_t)(ks * 16) * 2;
            uint32_t ah[4][4], al[4][4];
#pragma unroll
            for (int i = 0; i < 4; i++) {
                uint32_t ro = (uint32_t)(i * 16 * LDS) * 2;
                ldm_x4(ah[i], uAh + aoff + ro + kof);
                ldm_x4(al[i], uAl + aoff + ro + kof);
            }
            uint32_t bhf[4][2], blf[4][2];
#pragma unroll
            for (int j = 0; j < 4; j++) {
                uint32_t ro = (uint32_t)(j * 8 * LDS) * 2;
                ldm_x2(bhf[j], uBh + boff + ro + kof);
                ldm_x2(blf[j], uBl + boff + ro + kof);
            }
#pragma unroll
            for (int i = 0; i < 4; i++)
#pragma unroll
                for (int j = 0; j < 4; j++) {
                    mma_bf16(acc[i][j], ah[i], bhf[j]);
                    mma_bf16(acc[i][j], ah[i], blf[j]);
                    mma_bf16(acc[i][j], al[i], bhf[j]);
                }
        }
        __syncthreads();   // stage[stg] fully consumed
        if (c + 2 < NC) issue(c + 2);
    }

    // ---- epilogue (verbatim from proven kernel) ----
    float g = 0.0f;
    if (epi == 2) g = 1.0f / (1.0f + expf(-skipp[0]));

#pragma unroll
    for (int i = 0; i < 4; i++) {
#pragma unroll
        for (int half = 0; half < 2; half++) {
            int m = row0 + wm * 64 + i * 16 + (lane >> 2) + half * 8;
            if (m >= M) continue;
            size_t rb = (size_t)m * N;
#pragma unroll
            for (int j = 0; j < 4; j++) {
                int n = col0 + wn * 32 + j * 8 + (lane & 3) * 2;
                float v0 = acc[i][j][half * 2 + 0] + bias[n];
                float v1 = acc[i][j][half * 2 + 1] + bias[n + 1];
                if (epi == 1) {
                    v0 = (v0 > 0.f) ? v0 : 0.01f * v0;
                    v1 = (v1 > 0.f) ? v1 : 0.01f * v1;
                } else if (epi == 2) {
                    __nv_bfloat162 xh2 = *(const __nv_bfloat162*)(Xh + rb + n);
                    __nv_bfloat162 xl2 = *(const __nv_bfloat162*)(Xl + rb + n);
                    float x0 = __bfloat162float(xh2.x) + __bfloat162float(xl2.x);
                    float x1 = __bfloat162float(xh2.y) + __bfloat162float(xl2.y);
                    v0 = g * v0 + (1.f - g) * x0;
                    v1 = g * v1 + (1.f - g) * x1;
                }
                if (outmode == 2) {
                    __nv_bfloat16 ch0 = __float2bfloat16(v0);
                    __nv_bfloat16 ch1 = __float2bfloat16(v1);
                    __nv_bfloat162 co; co.x = ch0; co.y = ch1;
                    *(__nv_bfloat162*)(Ch + rb + n) = co;
                    __nv_bfloat162 cl;
                    cl.x = __float2bfloat16(v0 - __bfloat162float(ch0));
                    cl.y = __float2bfloat16(v1 - __bfloat162float(ch1));
                    *(__nv_bfloat162*)(Cl + rb + n) = cl;
                } else if (outmode == 1) {
                    *(__half2*)((__half*)C + rb + n) = __floats2half2_rn(v0, v1);
                } else {
                    float2 o; o.x = v0; o.y = v1;
                    *(float2*)(C + rb + n) = o;
                }
            }
        }
    }
}

// ---------------------------------------------------------------------------
// Async GEMM (templated on NTERMS): A pre-split bf16 hi/lo [M][256].
// 2-stage cp.async pipeline, K fixed at 256. Last-chunk wait fixed to wait0.
// ---------------------------------------------------------------------------
#define ATILE (128 * LDS)         // halves per tile (5120)
#define ASTG  (4 * ATILE)         // halves per stage (20480)
#define DSMEM_A (2 * ASTG * 2)    // bytes (81920)

template <int NTERMS>
__global__ __launch_bounds__(256)
void gemm_async(const __nv_bfloat16* __restrict__ Ah,
                const __nv_bfloat16* __restrict__ Al,
                const __nv_bfloat16* __restrict__ Bh,
                const __nv_bfloat16* __restrict__ Bl,
                const float* __restrict__ bias, float* __restrict__ C,
                int M, int N, int epi, int outmode)
{
    extern __shared__ __align__(16) __nv_bfloat16 sm[];
    const uint32_t smb = smem_u32(sm);

    const int tid  = threadIdx.x;
    const int wid  = tid >> 5;
    const int lane = tid & 31;
    const int wm   = wid >> 2;
    const int wn   = wid & 3;
    const int row0 = blockIdx.y * 128;
    const int col0 = blockIdx.x * 128;
    const int K = 256;

    const int a_r = (lane & 7) + ((lane >> 3) & 1) * 8;
    const int a_c = ((lane >> 4) & 1) * 8;
    const int b_r = (lane & 7);
    const int b_c = ((lane >> 3) & 1) * 8;
    const uint32_t aoff = (uint32_t)((wm * 64 + a_r) * LDS + a_c) * 2;
    const uint32_t boff = (uint32_t)((wn * 32 + b_r) * LDS + b_c) * 2;

    float acc[4][4][4];
#pragma unroll
    for (int i = 0; i < 4; i++)
#pragma unroll
        for (int j = 0; j < 4; j++)
#pragma unroll
            for (int r = 0; r < 4; r++) acc[i][j][r] = 0.0f;

    const int NC = 8;

    auto issue = [&](int stage, int chunk) {
        const int kb = chunk * 32;
#pragma unroll
        for (int i = 0; i < 2; i++) {
            int cid = tid + i * 256;
            int row = cid >> 2;
            int seg = cid & 3;
            uint32_t dst = smb + (uint32_t)(stage * ASTG + row * LDS + seg * 8) * 2;
            const int ga = row0 + row;
            uint32_t pa = (ga < M) ? 16u : 0u;
            const __nv_bfloat16* sa = Ah + (size_t)ga * K + kb + seg * 8;
            const __nv_bfloat16* sl = Al + (size_t)ga * K + kb + seg * 8;
            const __nv_bfloat16* sb = Bh + (size_t)(col0 + row) * K + kb + seg * 8;
            const __nv_bfloat16* sc = Bl + (size_t)(col0 + row) * K + kb + seg * 8;
            CP_ASYNC16P(dst,                 sa, pa);
            CP_ASYNC16P(dst + ATILE * 2,     sl, pa);
            CP_ASYNC16P(dst + 2 * ATILE * 2, sb, 16u);
            CP_ASYNC16P(dst + 3 * ATILE * 2, sc, 16u);
        }
        CP_COMMIT();
    };

    issue(0, 0);
    issue(1, 1);

    for (int c = 0; c < NC; c++) {
        const int st = c & 1;
        if (c >= NC - 1) CP_WAIT0(); else CP_WAIT1();
        __syncthreads();

        const uint32_t base = smb + (uint32_t)(st * ASTG) * 2;
        const uint32_t uAh = base;
        const uint32_t uAl = base + ATILE * 2;
        const uint32_t uBh = base + 2 * ATILE * 2;
        const uint32_t uBl = base + 3 * ATILE * 2;
#pragma unroll
        for (int ks = 0; ks < 2; ks++) {
            const uint32_t kof = (uint32_t)(ks * 16) * 2;
            uint32_t ah[4][4], al[4][4];
#pragma unroll
            for (int i = 0; i < 4; i++) {
                uint32_t ro = (uint32_t)(i * 16 * LDS) * 2;
                ldm_x4(ah[i], uAh + aoff + ro + kof);
                if (NTERMS == 3) ldm_x4(al[i], uAl + aoff + ro + kof);
            }
            uint32_t bhf[4][2], blf[4][2];
#pragma unroll
            for (int j = 0; j < 4; j++) {
                uint32_t ro = (uint32_t)(j * 8 * LDS) * 2;
                ldm_x2(bhf[j], uBh + boff + ro + kof);
                ldm_x2(blf[j], uBl + boff + ro + kof);
            }
#pragma unroll
            for (int i = 0; i < 4; i++)
#pragma unroll
                for (int j = 0; j < 4; j++) {
                    mma_bf16(acc[i][j], ah[i], bhf[j]);
                    mma_bf16(acc[i][j], ah[i], blf[j]);
                    if (NTERMS == 3) mma_bf16(acc[i][j], al[i], bhf[j]);
                }
        }
        __syncthreads();
        if (c + 2 < NC) issue(st, c + 2);
    }

    // ---- epilogue ----
#pragma unroll
    for (int i = 0; i < 4; i++) {
#pragma unroll
        for (int half = 0; half < 2; half++) {
            int m = row0 + wm * 64 + i * 16 + (lane >> 2) + half * 8;
            if (m >= M) continue;
            size_t rb = (size_t)m * N;
#pragma unroll
            for (int j = 0; j < 4; j++) {
                int n = col0 + wn * 32 + j * 8 + (lane & 3) * 2;
                float v0 = acc[i][j][half * 2 + 0] + bias[n];
                float v1 = acc[i][j][half * 2 + 1] + bias[n + 1];
                if (epi == 1) {
                    v0 = (v0 > 0.f) ? v0 : 0.01f * v0;
                    v1 = (v1 > 0.f) ? v1 : 0.01f * v1;
                }
                if (outmode == 1) {
                    *(__half2*)((__half*)C + rb + n) = __floats2half2_rn(v0, v1);
                } else {
                    float2 o; o.x = v0; o.y = v1;
                    *(float2*)(C + rb + n) = o;
                }
            }
        }
    }
}

// ---------------------------------------------------------------------------
// Fused edge logits + exp + denominator (fp16 KR/Q, verified R10-R13).
// ---------------------------------------------------------------------------
__global__ __launch_bounds__(256)
void logits_k(const __half* __restrict__ KR, const __half* __restrict__ Q,
              const int* __restrict__ src, const int* __restrict__ dst,
              const float* __restrict__ prel, float* __restrict__ expv,
              float* __restrict__ den, int E, int dst_off)
{
    int w    = (blockIdx.x * 256 + threadIdx.x) >> 5;
    int lane = threadIdx.x & 31;
    if (w >= E) return;
    int r = src[w], c = dst[w];
    const __half* kp = KR + (size_t)r * HID;
    const __half* qp = Q + (size_t)(dst_off + c) * HID;
    const float inv = 0.17677669529663687f;

    uint4 kv = *(const uint4*)(kp + lane * 8);
    uint4 qv = *(const uint4*)(qp + lane * 8);
    const __half2* k2 = (const __half2*)&kv;
    const __half2* q2 = (const __half2*)&qv;
    float v = 0.0f;
#pragma unroll
    for (int i = 0; i < 4; i++) {
        float2 a = __half22float2(k2[i]);
        float2 b = __half22float2(q2[i]);
        v += a.x * b.x + a.y * b.y;
    }
    v += __shfl_down_sync(0xffffffffu, v, 2);
    v += __shfl_down_sync(0xffffffffu, v, 1);
    if ((lane & 3) == 0) {
        int h = lane >> 2;
        float ex = expf(v * prel[h] * inv);
        expv[(size_t)w * NH + h] = ex;
        atomicAdd(&den[(size_t)c * NH + h], ex);
    }
}

// ---------------------------------------------------------------------------
// Message scatter (verified R9-R13).
// ---------------------------------------------------------------------------
__global__ __launch_bounds__(256)
void msg_k(const float* __restrict__ VR, const int* __restrict__ src,
           const int* __restrict__ dst, const float* __restrict__ exv,
           const float* __restrict__ den, float* __restrict__ out,
           int E, int dst_off)
{
    int eid = blockIdx.x * 4 + (threadIdx.x >> 6);
    if (eid >= E) return;
    int j = threadIdx.x & 63;
    int h = j >> 3;
    int r = src[eid], c = dst[eid];
    float attn = exv[(size_t)eid * NH + h] / (den[(size_t)c * NH + h] + 1e-16f);
    float4 v = *(const float4*)(VR + (size_t)r * HID + j * 4);
    v.x *= attn; v.y *= attn; v.z *= attn; v.w *= attn;
    float* dp = out + (size_t)(dst_off + c) * HID + j * 4;
    asm volatile("red.global.add.v4.f32 [%0], {%1,%2,%3,%4};"
                 :: "l"(dp), "f"(v.x), "f"(v.y), "f"(v.z), "f"(v.w)
                 : "memory");
}

// ---------------------------------------------------------------------------
// Host orchestration
// ---------------------------------------------------------------------------
extern "C" void kernel_launch(void* const* d_in, const int* in_sizes, int n_in,
                              void* d_out, int out_size)
{
    (void)n_in; (void)out_size;

    const float* xin[3] = { (const float*)d_in[0], (const float*)d_in[1],
                            (const float*)d_in[2] };
    const int* srcs[3] = { (const int*)d_in[3], (const int*)d_in[5], (const int*)d_in[7] };
    const int* dsts[3] = { (const int*)d_in[4], (const int*)d_in[6], (const int*)d_in[8] };
    int Es[3]   = { in_sizes[3], in_sizes[5], in_sizes[7] };
    int styp[3] = { 1, 0, 2 };
    int dtyp[3] = { 2, 2, 0 };

    int Nn[3] = { in_sizes[0] / INC, in_sizes[1] / INC, in_sizes[2] / INC };
    size_t off[3] = { 0, (size_t)Nn[0], (size_t)Nn[0] + (size_t)Nn[1] };
    size_t ntot = off[2] + (size_t)Nn[2];

    const float* W1    = (const float*)d_in[9];
    const float* b1    = (const float*)d_in[10];
    const float* W2    = (const float*)d_in[11];
    const float* b2    = (const float*)d_in[12];
    const float* Wk    = (const float*)d_in[13];
    const float* bk    = (const float*)d_in[14];
    const float* Wq    = (const float*)d_in[15];
    const float* bq    = (const float*)d_in[16];
    const float* Wv    = (const float*)d_in[17];
    const float* bv    = (const float*)d_in[18];
    const float* Wa    = (const float*)d_in[19];
    const float* ba    = (const float*)d_in[20];
    const float* skp   = (const float*)d_in[21];
    const float* a_rel = (const float*)d_in[22];
    const float* m_rel = (const float*)d_in[23];
    const float* p_rel = (const float*)d_in[24];

    float *xf, *x2f, *Qb, *ob, *kr, *vr, *lg, *dn, *We, *be;
    __nv_bfloat16 *bh, *bl;
    cudaGetSymbolAddress((void**)&xf,  g_x);
    cudaGetSymbolAddress((void**)&x2f, g_x2);
    cudaGetSymbolAddress((void**)&Qb, g_Q);
    cudaGetSymbolAddress((void**)&ob, g_o);
    cudaGetSymbolAddress((void**)&kr, g_kr);
    cudaGetSymbolAddress((void**)&vr, g_vr);
    cudaGetSymbolAddress((void**)&lg, g_lg);
    cudaGetSymbolAddress((void**)&dn, g_dn);
    cudaGetSymbolAddress((void**)&We, g_we);
    cudaGetSymbolAddress((void**)&be, g_be);
    cudaGetSymbolAddress((void**)&bh, g_bh);
    cudaGetSymbolAddress((void**)&bl, g_bl);

    __nv_bfloat16* xh = (__nv_bfloat16*)xf;   // activation hi
    __nv_bfloat16* xl = (__nv_bfloat16*)x2f;  // activation lo

    cudaFuncSetAttribute(gemm_async<3>,
                         cudaFuncAttributeMaxDynamicSharedMemorySize, DSMEM_A);
    cudaFuncSetAttribute(gemm_async<2>,
                         cudaFuncAttributeMaxDynamicSharedMemorySize, DSMEM_A);
    cudaFuncSetAttribute(gemm_cvt,
                         cudaFuncAttributeMaxDynamicSharedMemorySize, DSMEM_C);

    // ---- prep: fold relations, then transpose+split all weights -----------
    wtrans_k<<<2 * LAY * 3 * NH, 256>>>(Wk, bk, Wv, bv, a_rel, m_rel, We, be);
    wsplit_k<<<768, 256>>>(W1, bh + WB_W1, bl + WB_W1, 768, 256);
    wsplit_all<<<6272, 256>>>(Wq, We, Wa, W2, bh, bl);

    // ---- input MLP: pair = split(lrelu(x @ W1 + b1))  (async convert) -----
    for (int t = 0; t < 3; t++) {
        dim3 grid(HID / 128, (Nn[t] + 127) / 128);
        gemm_cvt<<<grid, 256, DSMEM_C>>>(xin[t], bh + WB_W1, bl + WB_W1, b1,
                                         nullptr, nullptr, nullptr, nullptr,
                                         xh + off[t] * HID, xl + off[t] * HID,
                                         Nn[t], HID, INC, 0, 1, 2);
    }

    for (int l = 0; l < 2; l++) {
        // ---- Q projections (async<2>; only dst types review/user) ---------
        for (int t = 0; t < 3; t++) {
            if (t == 1) continue;
            size_t wo = WB_WQ + (size_t)(l * 3 + t) * 65536;
            dim3 grid(HID / 128, (Nn[t] + 127) / 128);
            gemm_async<2><<<grid, 256, DSMEM_A>>>(
                xh + off[t] * HID, xl + off[t] * HID, bh + wo, bl + wo,
                bq + (size_t)(l * 3 + t) * HID,
                (float*)((__half*)Qb + off[t] * HID), Nn[t], HID, 0, 1);
        }

        // ---- per-edge-type attention + aggregation ------------------------
        cudaMemsetAsync(ob, 0, ntot * HID * sizeof(float), 0);
        for (int e = 0; e < 3; e++) {
            int s = styp[e], t = dtyp[e];
            if (Es[e] <= 0) continue;

            size_t ik = WB_WE + (size_t)((0 * LAY + l) * 3 + e) * 65536;
            size_t iv = WB_WE + (size_t)((1 * LAY + l) * 3 + e) * 65536;
            size_t bik = (size_t)((0 * LAY + l) * 3 + e) * HID;
            size_t biv = (size_t)((1 * LAY + l) * 3 + e) * HID;
            dim3 grid(HID / 128, (Nn[s] + 127) / 128);
            gemm_async<2><<<grid, 256, DSMEM_A>>>(
                xh + off[s] * HID, xl + off[s] * HID, bh + ik, bl + ik,
                be + bik, kr, Nn[s], HID, 0, 1);
            gemm_async<3><<<grid, 256, DSMEM_A>>>(
                xh + off[s] * HID, xl + off[s] * HID, bh + iv, bl + iv,
                be + biv, vr, Nn[s], HID, 0, 0);

            cudaMemsetAsync(dn, 0, (size_t)Nn[t] * NH * sizeof(float), 0);

            logits_k<<<(Es[e] * 32 + 255) / 256, 256>>>(
                (const __half*)kr, (const __half*)Qb, srcs[e], dsts[e],
                p_rel + (size_t)(l * 3 + e) * NH, lg, dn, Es[e], (int)off[t]);
            msg_k<<<(Es[e] + 3) / 4, 256>>>(vr, srcs[e], dsts[e], lg, dn, ob,
                                            Es[e], (int)off[t]);
        }

        // ---- output projection + gated skip (async convert, pair IO) ------
        for (int t = 0; t < 3; t++) {
            size_t wo = WB_WA + (size_t)(l * 3 + t) * 65536;
            dim3 grid(HID / 128, (Nn[t] + 127) / 128);
            gemm_cvt<<<grid, 256, DSMEM_C>>>(ob + off[t] * HID, bh + wo, bl + wo,
                                             ba + (size_t)(l * 3 + t) * HID,
                                             xh + off[t] * HID, xl + off[t] * HID,
                                             skp + (l * 3 + t), nullptr,
                                             xh + off[t] * HID, xl + off[t] * HID,
                                             Nn[t], HID, HID, 1, 2, 2);
        }
    }

    // ---- final MLP (async<3>): lrelu(x @ W2 + b2), concatenated -----------
    float* outp = (float*)d_out;
    for (int t = 0; t < 3; t++) {
        dim3 grid(OUTC / 128, (Nn[t] + 127) / 128);
        gemm_async<3><<<grid, 256, DSMEM_A>>>(
            xh + off[t] * HID, xl + off[t] * HID, bh + WB_W2, bl + WB_W2,
            b2, outp + off[t] * OUTC, Nn[t], OUTC, 1, 0);
    }
}

// round 15
// speedup vs baseline: 1.4883x; 1.4883x over previous
#include <cuda_runtime.h>
#include <cuda_bf16.h>
#include <cuda_fp16.h>
#include <math.h>
#include <stdint.h>

// ---------------------------------------------------------------------------
// Problem constants
// ---------------------------------------------------------------------------
#define NH    8
#define DH    32
#define HID   256
#define INC   768
#define OUTC  128
#define NTOT  270000
#define NRMAX 200000
#define EMAX  200000
#define LAY   2

// ---------------------------------------------------------------------------
// Scratch (static device globals; allocation APIs forbidden). ~1.53 GB.
// ---------------------------------------------------------------------------
__device__ float g_x  [(size_t)NTOT * HID];   // used as bf16 hi activations
__device__ float g_x2 [(size_t)NTOT * HID];   // used as bf16 lo activations
__device__ float g_Q  [(size_t)NTOT * HID];   // used as __half
__device__ float g_o  [(size_t)NTOT * HID];   // fp32 attention accum
__device__ float g_kr [(size_t)NRMAX * HID];  // used as __half
__device__ float g_vr [(size_t)NRMAX * HID];  // used as __half
__device__ float g_lg [(size_t)EMAX * NH];
__device__ float g_dn [(size_t)NRMAX * NH];
// relation-folded K/V weights (fp32, [K][N])
__device__ float g_we [(size_t)2 * LAY * 3 * HID * HID];
__device__ float g_be [(size_t)2 * LAY * 3 * HID];
// all GEMM weights, transposed to [N][K], split into bf16 hi/lo
#define WB_W1 0
#define WB_WQ (WB_W1 + 256*768)
#define WB_WE (WB_WQ + 6*256*256)
#define WB_WA (WB_WE + 12*256*256)
#define WB_W2 (WB_WA + 6*256*256)
#define WB_TOT (WB_W2 + 128*256)
__device__ __nv_bfloat16 g_bh[WB_TOT];
__device__ __nv_bfloat16 g_bl[WB_TOT];

// ---------------------------------------------------------------------------
// Helpers
// ---------------------------------------------------------------------------
__device__ __forceinline__ uint32_t smem_u32(const void* p) {
    uint32_t a;
    asm("{ .reg .u64 t; cvta.to.shared.u64 t, %1; cvt.u32.u64 %0, t; }"
        : "=r"(a) : "l"(p));
    return a;
}
__device__ __forceinline__ float geluf(float v) {
    return 0.5f * v * (1.0f + erff(v * 0.70710678118654752f));
}

__device__ __forceinline__ void mma_bf16(float* c, const uint32_t* a,
                                         const uint32_t* b) {
    asm volatile(
        "mma.sync.aligned.m16n8k16.row.col.f32.bf16.bf16.f32 "
        "{%0,%1,%2,%3}, {%4,%5,%6,%7}, {%8,%9}, {%0,%1,%2,%3};\n"
        : "+f"(c[0]), "+f"(c[1]), "+f"(c[2]), "+f"(c[3])
        : "r"(a[0]), "r"(a[1]), "r"(a[2]), "r"(a[3]), "r"(b[0]), "r"(b[1]));
}
__device__ __forceinline__ void ldm_x4(uint32_t* r, uint32_t addr) {
    asm volatile("ldmatrix.sync.aligned.m8n8.x4.shared.b16 {%0,%1,%2,%3}, [%4];"
        : "=r"(r[0]), "=r"(r[1]), "=r"(r[2]), "=r"(r[3]) : "r"(addr));
}
__device__ __forceinline__ void ldm_x2(uint32_t* r, uint32_t addr) {
    asm volatile("ldmatrix.sync.aligned.m8n8.x2.shared.b16 {%0,%1}, [%2];"
        : "=r"(r[0]), "=r"(r[1]) : "r"(addr));
}
#define CP_ASYNC16P(dst, src, p) \
    asm volatile("cp.async.cg.shared.global [%0], [%1], 16, %2;" \
                 :: "r"(dst), "l"(src), "r"(p))
#define CP_COMMIT() asm volatile("cp.async.commit_group;" ::: "memory")
#define CP_WAIT1()  asm volatile("cp.async.wait_group 1;" ::: "memory")
#define CP_WAIT0()  asm volatile("cp.async.wait_group 0;" ::: "memory")

// ---------------------------------------------------------------------------
// Fold relation matrices into K/V projection weights (verified R3-R14)
// ---------------------------------------------------------------------------
__global__ __launch_bounds__(256)
void wtrans_k(const float* __restrict__ Wk, const float* __restrict__ bk,
              const float* __restrict__ Wv, const float* __restrict__ bv,
              const float* __restrict__ a_rel, const float* __restrict__ m_rel,
              float* __restrict__ We, float* __restrict__ be)
{
    const int styp[3] = { 1, 0, 2 };
    int idx = blockIdx.x;
    int h   = idx & 7;
    int e   = (idx >> 3) % 3;
    int l   = ((idx >> 3) / 3) % LAY;
    int kv  = idx / (8 * 3 * LAY);
    int s   = styp[e];

    const float* W = (kv == 0 ? Wk : Wv) + (size_t)(l * 3 + s) * HID * HID;
    const float* b = (kv == 0 ? bk : bv) + (size_t)(l * 3 + s) * HID;
    const float* A = (kv == 0 ? a_rel : m_rel)
                   + ((size_t)(l * 3 + e) * NH + h) * DH * DH;
    float* Wo = We + (size_t)((kv * LAY + l) * 3 + e) * HID * HID;
    float* bo = be + (size_t)((kv * LAY + l) * 3 + e) * HID;

    __shared__ float sA[DH][DH];
    if (threadIdx.x < DH * DH / 2) {
        int d = threadIdx.x >> 4, c = (threadIdx.x & 15) * 2;
        sA[d][c]     = A[d * DH + c];
        sA[d][c + 1] = A[d * DH + c + 1];
        sA[d + 16][c]     = A[(d + 16) * DH + c];
        sA[d + 16][c + 1] = A[(d + 16) * DH + c + 1];
    }
    __syncthreads();

    int i = threadIdx.x;
    float w[DH];
#pragma unroll
    for (int d = 0; d < DH; d++) w[d] = W[(size_t)i * HID + h * DH + d];
#pragma unroll 4
    for (int c = 0; c < DH; c++) {
        float acc = 0.0f;
#pragma unroll
        for (int d = 0; d < DH; d++) acc += w[d] * sA[d][c];
        Wo[(size_t)i * HID + h * DH + c] = acc;
    }
    if (i < DH) {
        float acc = 0.0f;
#pragma unroll
        for (int d = 0; d < DH; d++) acc += b[h * DH + d] * sA[d][i];
        bo[h * DH + i] = acc;
    }
}

// ---------------------------------------------------------------------------
// Transpose + split fp32 weight [K][N] -> bf16 hi/lo [N][K] (W1 only)
// ---------------------------------------------------------------------------
__global__ __launch_bounds__(256)
void wsplit_k(const float* __restrict__ src, __nv_bfloat16* __restrict__ hi,
              __nv_bfloat16* __restrict__ lo, int K, int N)
{
    int i = blockIdx.x * 256 + threadIdx.x;
    if (i >= K * N) return;
    int n = i / K, k = i - n * K;
    float w = src[(size_t)k * N + n];
    __nv_bfloat16 h = __float2bfloat16(w);
    hi[i] = h;
    lo[i] = __float2bfloat16(w - __bfloat162float(h));
}

// ---------------------------------------------------------------------------
// Batched transpose+split for all K=256 weights: Wq(6) We(12) Wa(6) W2(1).
// ---------------------------------------------------------------------------
__global__ __launch_bounds__(256)
void wsplit_all(const float* __restrict__ Wq, const float* __restrict__ We,
                const float* __restrict__ Wa, const float* __restrict__ W2,
                __nv_bfloat16* __restrict__ bh, __nv_bfloat16* __restrict__ bl)
{
    int bid = blockIdx.x;
    const float* src;
    size_t off;
    int N, inner;
    if (bid < 6144) {
        int seg = bid >> 8;
        inner = ((bid & 255) << 8) | threadIdx.x;
        N = 256;
        if (seg < 6)       { src = Wq + (size_t)seg * 65536;        off = WB_WQ + (size_t)seg * 65536; }
        else if (seg < 18) { src = We + (size_t)(seg - 6) * 65536;  off = WB_WE + (size_t)(seg - 6) * 65536; }
        else               { src = Wa + (size_t)(seg - 18) * 65536; off = WB_WA + (size_t)(seg - 18) * 65536; }
    } else {
        inner = ((bid - 6144) << 8) | threadIdx.x;
        N = 128; src = W2; off = WB_W2;
    }
    int n = inner >> 8;
    int k = inner & 255;
    float w = src[(size_t)k * N + n];
    __nv_bfloat16 h = __float2bfloat16(w);
    bh[off + inner] = h;
    bl[off + inner] = __float2bfloat16(w - __bfloat162float(h));
}

#define LDS 40   // smem row stride in halves (80B: conflict-free ldmatrix)

// ---------------------------------------------------------------------------
// Proven convert-GEMM (fp32 A, in-kernel split; EXACT R13 kernel, 2 CTA/SM):
// outmode: 0 = fp32 C, 1 = __half C, 2 = bf16 hi/lo pair (Ch, Cl)
// epi=2 reads skip input from bf16 pair (Xh, Xl).
// ---------------------------------------------------------------------------
__global__ __launch_bounds__(256)
void gemm_mma(const float* __restrict__ A,
              const __nv_bfloat16* __restrict__ Bh,
              const __nv_bfloat16* __restrict__ Bl,
              const float* __restrict__ bias,
              const __nv_bfloat16* __restrict__ Xh,
              const __nv_bfloat16* __restrict__ Xl,
              const float* __restrict__ skipp, float* __restrict__ C,
              __nv_bfloat16* __restrict__ Ch, __nv_bfloat16* __restrict__ Cl,
              int M, int N, int K, int actA, int epi, int outmode)
{
    __shared__ __align__(16) __nv_bfloat16 sAh[128 * LDS];
    __shared__ __align__(16) __nv_bfloat16 sAl[128 * LDS];
    __shared__ __align__(16) __nv_bfloat16 sBh[128 * LDS];
    __shared__ __align__(16) __nv_bfloat16 sBl[128 * LDS];

    const int tid  = threadIdx.x;
    const int wid  = tid >> 5;
    const int lane = tid & 31;
    const int wm   = wid >> 2;
    const int wn   = wid & 3;
    const int row0 = blockIdx.y * 128;
    const int col0 = blockIdx.x * 128;

    const int lrow = tid >> 1;
    const int lk   = (tid & 1) * 16;
    const int aGR  = row0 + lrow;
    const bool av  = (aGR < M);
    const float* Arow = A + (size_t)aGR * K;
    const __nv_bfloat16* BHrow = Bh + (size_t)(col0 + lrow) * K;
    const __nv_bfloat16* BLrow = Bl + (size_t)(col0 + lrow) * K;

    const int a_r = (lane & 7) + ((lane >> 3) & 1) * 8;
    const int a_c = ((lane >> 4) & 1) * 8;
    const int b_r = (lane & 7);
    const int b_c = ((lane >> 3) & 1) * 8;

    const uint32_t uAh = smem_u32(sAh), uAl = smem_u32(sAl);
    const uint32_t uBh = smem_u32(sBh), uBl = smem_u32(sBl);
    const uint32_t aoff = (uint32_t)((wm * 64 + a_r) * LDS + a_c) * 2;
    const uint32_t boff = (uint32_t)((wn * 32 + b_r) * LDS + b_c) * 2;
    const uint32_t sto  = (uint32_t)(lrow * LDS + lk);

    float acc[4][4][4];
#pragma unroll
    for (int i = 0; i < 4; i++)
#pragma unroll
        for (int j = 0; j < 4; j++)
#pragma unroll
            for (int r = 0; r < 4; r++) acc[i][j][r] = 0.0f;

    const int NC = K / 32;
    for (int c = 0; c < NC; c++) {
        const int kb = c * 32 + lk;

        float4 f0, f1, f2, f3;
        if (av) {
            f0 = *(const float4*)(Arow + kb);
            f1 = *(const float4*)(Arow + kb + 4);
            f2 = *(const float4*)(Arow + kb + 8);
            f3 = *(const float4*)(Arow + kb + 12);
            if (actA) {
                f0.x = geluf(f0.x); f0.y = geluf(f0.y); f0.z = geluf(f0.z); f0.w = geluf(f0.w);
                f1.x = geluf(f1.x); f1.y = geluf(f1.y); f1.z = geluf(f1.z); f1.w = geluf(f1.w);
                f2.x = geluf(f2.x); f2.y = geluf(f2.y); f2.z = geluf(f2.z); f2.w = geluf(f2.w);
                f3.x = geluf(f3.x); f3.y = geluf(f3.y); f3.z = geluf(f3.z); f3.w = geluf(f3.w);
            }
        } else {
            f0 = make_float4(0.f, 0.f, 0.f, 0.f); f1 = f0; f2 = f0; f3 = f0;
        }
        uint4 bh0 = *(const uint4*)(BHrow + kb);
        uint4 bh1 = *(const uint4*)(BHrow + kb + 8);
        uint4 bl0 = *(const uint4*)(BLrow + kb);
        uint4 bl1 = *(const uint4*)(BLrow + kb + 8);

        if (c) __syncthreads();

        __nv_bfloat162 h0 = __floats2bfloat162_rn(f0.x, f0.y);
        __nv_bfloat162 h1 = __floats2bfloat162_rn(f0.z, f0.w);
        __nv_bfloat162 h2 = __floats2bfloat162_rn(f1.x, f1.y);
        __nv_bfloat162 h3 = __floats2bfloat162_rn(f1.z, f1.w);
        __nv_bfloat162 h4 = __floats2bfloat162_rn(f2.x, f2.y);
        __nv_bfloat162 h5 = __floats2bfloat162_rn(f2.z, f2.w);
        __nv_bfloat162 h6 = __floats2bfloat162_rn(f3.x, f3.y);
        __nv_bfloat162 h7 = __floats2bfloat162_rn(f3.z, f3.w);
        __nv_bfloat162 l0 = __floats2bfloat162_rn(f0.x - __bfloat162float(h0.x), f0.y - __bfloat162float(h0.y));
        __nv_bfloat162 l1 = __floats2bfloat162_rn(f0.z - __bfloat162float(h1.x), f0.w - __bfloat162float(h1.y));
        __nv_bfloat162 l2 = __floats2bfloat162_rn(f1.x - __bfloat162float(h2.x), f1.y - __bfloat162float(h2.y));
        __nv_bfloat162 l3 = __floats2bfloat162_rn(f1.z - __bfloat162float(h3.x), f1.w - __bfloat162float(h3.y));
        __nv_bfloat162 l4 = __floats2bfloat162_rn(f2.x - __bfloat162float(h4.x), f2.y - __bfloat162float(h4.y));
        __nv_bfloat162 l5 = __floats2bfloat162_rn(f2.z - __bfloat162float(h5.x), f2.w - __bfloat162float(h5.y));
        __nv_bfloat162 l6 = __floats2bfloat162_rn(f3.x - __bfloat162float(h6.x), f3.y - __bfloat162float(h6.y));
        __nv_bfloat162 l7 = __floats2bfloat162_rn(f3.z - __bfloat162float(h7.x), f3.w - __bfloat162float(h7.y));
        *(uint4*)&sAh[sto]     = make_uint4(*(uint32_t*)&h0, *(uint32_t*)&h1, *(uint32_t*)&h2, *(uint32_t*)&h3);
        *(uint4*)&sAh[sto + 8] = make_uint4(*(uint32_t*)&h4, *(uint32_t*)&h5, *(uint32_t*)&h6, *(uint32_t*)&h7);
        *(uint4*)&sAl[sto]     = make_uint4(*(uint32_t*)&l0, *(uint32_t*)&l1, *(uint32_t*)&l2, *(uint32_t*)&l3);
        *(uint4*)&sAl[sto + 8] = make_uint4(*(uint32_t*)&l4, *(uint32_t*)&l5, *(uint32_t*)&l6, *(uint32_t*)&l7);
        *(uint4*)&sBh[sto]     = bh0;
        *(uint4*)&sBh[sto + 8] = bh1;
        *(uint4*)&sBl[sto]     = bl0;
        *(uint4*)&sBl[sto + 8] = bl1;
        __syncthreads();

#pragma unroll
        for (int ks = 0; ks < 2; ks++) {
            const uint32_t kof = (uint32_t)(ks * 16) * 2;
            uint32_t ah[4][4], al[4][4];
#pragma unroll
            for (int i = 0; i < 4; i++) {
                uint32_t ro = (uint32_t)(i * 16 * LDS) * 2;
                ldm_x4(ah[i], uAh + aoff + ro + kof);
                ldm_x4(al[i], uAl + aoff + ro + kof);
            }
            uint32_t bhf[4][2], blf[4][2];
#pragma unroll
            for (int j = 0; j < 4; j++) {
                uint32_t ro = (uint32_t)(j * 8 * LDS) * 2;
                ldm_x2(bhf[j], uBh + boff + ro + kof);
                ldm_x2(blf[j], uBl + boff + ro + kof);
            }
#pragma unroll
            for (int i = 0; i < 4; i++)
#pragma unroll
                for (int j = 0; j < 4; j++) {
                    mma_bf16(acc[i][j], ah[i], bhf[j]);
                    mma_bf16(acc[i][j], ah[i], blf[j]);
                    mma_bf16(acc[i][j], al[i], bhf[j]);
                }
        }
    }

    float g = 0.0f;
    if (epi == 2) g = 1.0f / (1.0f + expf(-skipp[0]));

#pragma unroll
    for (int i = 0; i < 4; i++) {
#pragma unroll
        for (int half = 0; half < 2; half++) {
            int m = row0 + wm * 64 + i * 16 + (lane >> 2) + half * 8;
            if (m >= M) continue;
            size_t rb = (size_t)m * N;
#pragma unroll
            for (int j = 0; j < 4; j++) {
                int n = col0 + wn * 32 + j * 8 + (lane & 3) * 2;
                float v0 = acc[i][j][half * 2 + 0] + bias[n];
                float v1 = acc[i][j][half * 2 + 1] + bias[n + 1];
                if (epi == 1) {
                    v0 = (v0 > 0.f) ? v0 : 0.01f * v0;
                    v1 = (v1 > 0.f) ? v1 : 0.01f * v1;
                } else if (epi == 2) {
                    __nv_bfloat162 xh2 = *(const __nv_bfloat162*)(Xh + rb + n);
                    __nv_bfloat162 xl2 = *(const __nv_bfloat162*)(Xl + rb + n);
                    float x0 = __bfloat162float(xh2.x) + __bfloat162float(xl2.x);
                    float x1 = __bfloat162float(xh2.y) + __bfloat162float(xl2.y);
                    v0 = g * v0 + (1.f - g) * x0;
                    v1 = g * v1 + (1.f - g) * x1;
                }
                if (outmode == 2) {
                    __nv_bfloat16 ch0 = __float2bfloat16(v0);
                    __nv_bfloat16 ch1 = __float2bfloat16(v1);
                    __nv_bfloat162 co; co.x = ch0; co.y = ch1;
                    *(__nv_bfloat162*)(Ch + rb + n) = co;
                    __nv_bfloat162 cl;
                    cl.x = __float2bfloat16(v0 - __bfloat162float(ch0));
                    cl.y = __float2bfloat16(v1 - __bfloat162float(ch1));
                    *(__nv_bfloat162*)(Cl + rb + n) = cl;
                } else if (outmode == 1) {
                    *(__half2*)((__half*)C + rb + n) = __floats2half2_rn(v0, v1);
                } else {
                    float2 o; o.x = v0; o.y = v1;
                    *(float2*)(C + rb + n) = o;
                }
            }
        }
    }
}

// ---------------------------------------------------------------------------
// Async GEMM (templated on NTERMS): A pre-split bf16 hi/lo [M][256].
// 2-stage cp.async pipeline, K fixed at 256. Last-chunk wait0 (exact).
// ---------------------------------------------------------------------------
#define ATILE (128 * LDS)         // halves per tile (5120)
#define ASTG  (4 * ATILE)         // halves per stage (20480)
#define DSMEM_A (2 * ASTG * 2)    // bytes (81920)

template <int NTERMS>
__global__ __launch_bounds__(256)
void gemm_async(const __nv_bfloat16* __restrict__ Ah,
                const __nv_bfloat16* __restrict__ Al,
                const __nv_bfloat16* __restrict__ Bh,
                const __nv_bfloat16* __restrict__ Bl,
                const float* __restrict__ bias, float* __restrict__ C,
                int M, int N, int epi, int outmode)
{
    extern __shared__ __align__(16) __nv_bfloat16 sm[];
    const uint32_t smb = smem_u32(sm);

    const int tid  = threadIdx.x;
    const int wid  = tid >> 5;
    const int lane = tid & 31;
    const int wm   = wid >> 2;
    const int wn   = wid & 3;
    const int row0 = blockIdx.y * 128;
    const int col0 = blockIdx.x * 128;
    const int K = 256;

    const int a_r = (lane & 7) + ((lane >> 3) & 1) * 8;
    const int a_c = ((lane >> 4) & 1) * 8;
    const int b_r = (lane & 7);
    const int b_c = ((lane >> 3) & 1) * 8;
    const uint32_t aoff = (uint32_t)((wm * 64 + a_r) * LDS + a_c) * 2;
    const uint32_t boff = (uint32_t)((wn * 32 + b_r) * LDS + b_c) * 2;

    float acc[4][4][4];
#pragma unroll
    for (int i = 0; i < 4; i++)
#pragma unroll
        for (int j = 0; j < 4; j++)
#pragma unroll
            for (int r = 0; r < 4; r++) acc[i][j][r] = 0.0f;

    const int NC = 8;

    auto issue = [&](int stage, int chunk) {
        const int kb = chunk * 32;
#pragma unroll
        for (int i = 0; i < 2; i++) {
            int cid = tid + i * 256;
            int row = cid >> 2;
            int seg = cid & 3;
            uint32_t dst = smb + (uint32_t)(stage * ASTG + row * LDS + seg * 8) * 2;
            const int ga = row0 + row;
            uint32_t pa = (ga < M) ? 16u : 0u;
            const __nv_bfloat16* sa = Ah + (size_t)ga * K + kb + seg * 8;
            const __nv_bfloat16* sl = Al + (size_t)ga * K + kb + seg * 8;
            const __nv_bfloat16* sb = Bh + (size_t)(col0 + row) * K + kb + seg * 8;
            const __nv_bfloat16* sc = Bl + (size_t)(col0 + row) * K + kb + seg * 8;
            CP_ASYNC16P(dst,                 sa, pa);
            CP_ASYNC16P(dst + ATILE * 2,     sl, pa);
            CP_ASYNC16P(dst + 2 * ATILE * 2, sb, 16u);
            CP_ASYNC16P(dst + 3 * ATILE * 2, sc, 16u);
        }
        CP_COMMIT();
    };

    issue(0, 0);
    issue(1, 1);

    for (int c = 0; c < NC; c++) {
        const int st = c & 1;
        if (c >= NC - 1) CP_WAIT0(); else CP_WAIT1();
        __syncthreads();

        const uint32_t base = smb + (uint32_t)(st * ASTG) * 2;
        const uint32_t uAh = base;
        const uint32_t uAl = base + ATILE * 2;
        const uint32_t uBh = base + 2 * ATILE * 2;
        const uint32_t uBl = base + 3 * ATILE * 2;
#pragma unroll
        for (int ks = 0; ks < 2; ks++) {
            const uint32_t kof = (uint32_t)(ks * 16) * 2;
            uint32_t ah[4][4], al[4][4];
#pragma unroll
            for (int i = 0; i < 4; i++) {
                uint32_t ro = (uint32_t)(i * 16 * LDS) * 2;
                ldm_x4(ah[i], uAh + aoff + ro + kof);
                if (NTERMS == 3) ldm_x4(al[i], uAl + aoff + ro + kof);
            }
            uint32_t bhf[4][2], blf[4][2];
#pragma unroll
            for (int j = 0; j < 4; j++) {
                uint32_t ro = (uint32_t)(j * 8 * LDS) * 2;
                ldm_x2(bhf[j], uBh + boff + ro + kof);
                ldm_x2(blf[j], uBl + boff + ro + kof);
            }
#pragma unroll
            for (int i = 0; i < 4; i++)
#pragma unroll
                for (int j = 0; j < 4; j++) {
                    mma_bf16(acc[i][j], ah[i], bhf[j]);
                    mma_bf16(acc[i][j], ah[i], blf[j]);
                    if (NTERMS == 3) mma_bf16(acc[i][j], al[i], bhf[j]);
                }
        }
        __syncthreads();
        if (c + 2 < NC) issue(st, c + 2);
    }

    // ---- epilogue ----
#pragma unroll
    for (int i = 0; i < 4; i++) {
#pragma unroll
        for (int half = 0; half < 2; half++) {
            int m = row0 + wm * 64 + i * 16 + (lane >> 2) + half * 8;
            if (m >= M) continue;
            size_t rb = (size_t)m * N;
#pragma unroll
            for (int j = 0; j < 4; j++) {
                int n = col0 + wn * 32 + j * 8 + (lane & 3) * 2;
                float v0 = acc[i][j][half * 2 + 0] + bias[n];
                float v1 = acc[i][j][half * 2 + 1] + bias[n + 1];
                if (epi == 1) {
                    v0 = (v0 > 0.f) ? v0 : 0.01f * v0;
                    v1 = (v1 > 0.f) ? v1 : 0.01f * v1;
                }
                if (outmode == 1) {
                    *(__half2*)((__half*)C + rb + n) = __floats2half2_rn(v0, v1);
                } else {
                    float2 o; o.x = v0; o.y = v1;
                    *(float2*)(C + rb + n) = o;
                }
            }
        }
    }
}

// ---------------------------------------------------------------------------
// Fused edge logits + exp + denominator (fp16 KR/Q, verified R10-R14).
// ---------------------------------------------------------------------------
__global__ __launch_bounds__(256)
void logits_k(const __half* __restrict__ KR, const __half* __restrict__ Q,
              const int* __restrict__ src, const int* __restrict__ dst,
              const float* __restrict__ prel, float* __restrict__ expv,
              float* __restrict__ den, int E, int dst_off)
{
    int w    = (blockIdx.x * 256 + threadIdx.x) >> 5;
    int lane = threadIdx.x & 31;
    if (w >= E) return;
    int r = src[w], c = dst[w];
    const __half* kp = KR + (size_t)r * HID;
    const __half* qp = Q + (size_t)(dst_off + c) * HID;
    const float inv = 0.17677669529663687f;

    uint4 kv = *(const uint4*)(kp + lane * 8);
    uint4 qv = *(const uint4*)(qp + lane * 8);
    const __half2* k2 = (const __half2*)&kv;
    const __half2* q2 = (const __half2*)&qv;
    float v = 0.0f;
#pragma unroll
    for (int i = 0; i < 4; i++) {
        float2 a = __half22float2(k2[i]);
        float2 b = __half22float2(q2[i]);
        v += a.x * b.x + a.y * b.y;
    }
    v += __shfl_down_sync(0xffffffffu, v, 2);
    v += __shfl_down_sync(0xffffffffu, v, 1);
    if ((lane & 3) == 0) {
        int h = lane >> 2;
        float ex = expf(v * prel[h] * inv);
        expv[(size_t)w * NH + h] = ex;
        atomicAdd(&den[(size_t)c * NH + h], ex);
    }
}

// ---------------------------------------------------------------------------
// Message scatter (fp16 VR): out[dst, :] += vr[src, :] * attn.
// Warp per edge; each lane covers 8 halves; 2x red.global.add.v4.f32.
// ---------------------------------------------------------------------------
__global__ __launch_bounds__(256)
void msg_k(const __half* __restrict__ VR, const int* __restrict__ src,
           const int* __restrict__ dst, const float* __restrict__ exv,
           const float* __restrict__ den, float* __restrict__ out,
           int E, int dst_off)
{
    int eid = blockIdx.x * 8 + (threadIdx.x >> 5);
    if (eid >= E) return;
    int j = threadIdx.x & 31;          // covers halves [8j, 8j+8)
    int h = j >> 2;                    // 4 lanes per 32-wide head
    int r = src[eid], c = dst[eid];
    float attn = exv[(size_t)eid * NH + h] / (den[(size_t)c * NH + h] + 1e-16f);
    uint4 v = *(const uint4*)(VR + (size_t)r * HID + j * 8);
    const __half2* v2 = (const __half2*)&v;
    float2 f0 = __half22float2(v2[0]);
    float2 f1 = __half22float2(v2[1]);
    float2 f2 = __half22float2(v2[2]);
    float2 f3 = __half22float2(v2[3]);
    f0.x *= attn; f0.y *= attn; f1.x *= attn; f1.y *= attn;
    f2.x *= attn; f2.y *= attn; f3.x *= attn; f3.y *= attn;
    float* dp = out + (size_t)(dst_off + c) * HID + j * 8;
    asm volatile("red.global.add.v4.f32 [%0], {%1,%2,%3,%4};"
                 :: "l"(dp), "f"(f0.x), "f"(f0.y), "f"(f1.x), "f"(f1.y)
                 : "memory");
    asm volatile("red.global.add.v4.f32 [%0], {%1,%2,%3,%4};"
                 :: "l"(dp + 4), "f"(f2.x), "f"(f2.y), "f"(f3.x), "f"(f3.y)
                 : "memory");
}

// ---------------------------------------------------------------------------
// Host orchestration
// ---------------------------------------------------------------------------
extern "C" void kernel_launch(void* const* d_in, const int* in_sizes, int n_in,
                              void* d_out, int out_size)
{
    (void)n_in; (void)out_size;

    const float* xin[3] = { (const float*)d_in[0], (const float*)d_in[1],
                            (const float*)d_in[2] };
    const int* srcs[3] = { (const int*)d_in[3], (const int*)d_in[5], (const int*)d_in[7] };
    const int* dsts[3] = { (const int*)d_in[4], (const int*)d_in[6], (const int*)d_in[8] };
    int Es[3]   = { in_sizes[3], in_sizes[5], in_sizes[7] };
    int styp[3] = { 1, 0, 2 };
    int dtyp[3] = { 2, 2, 0 };

    int Nn[3] = { in_sizes[0] / INC, in_sizes[1] / INC, in_sizes[2] / INC };
    size_t off[3] = { 0, (size_t)Nn[0], (size_t)Nn[0] + (size_t)Nn[1] };
    size_t ntot = off[2] + (size_t)Nn[2];

    const float* W1    = (const float*)d_in[9];
    const float* b1    = (const float*)d_in[10];
    const float* W2    = (const float*)d_in[11];
    const float* b2    = (const float*)d_in[12];
    const float* Wk    = (const float*)d_in[13];
    const float* bk    = (const float*)d_in[14];
    const float* Wq    = (const float*)d_in[15];
    const float* bq    = (const float*)d_in[16];
    const float* Wv    = (const float*)d_in[17];
    const float* bv    = (const float*)d_in[18];
    const float* Wa    = (const float*)d_in[19];
    const float* ba    = (const float*)d_in[20];
    const float* skp   = (const float*)d_in[21];
    const float* a_rel = (const float*)d_in[22];
    const float* m_rel = (const float*)d_in[23];
    const float* p_rel = (const float*)d_in[24];

    float *xf, *x2f, *Qb, *ob, *kr, *vr, *lg, *dn, *We, *be;
    __nv_bfloat16 *bh, *bl;
    cudaGetSymbolAddress((void**)&xf,  g_x);
    cudaGetSymbolAddress((void**)&x2f, g_x2);
    cudaGetSymbolAddress((void**)&Qb, g_Q);
    cudaGetSymbolAddress((void**)&ob, g_o);
    cudaGetSymbolAddress((void**)&kr, g_kr);
    cudaGetSymbolAddress((void**)&vr, g_vr);
    cudaGetSymbolAddress((void**)&lg, g_lg);
    cudaGetSymbolAddress((void**)&dn, g_dn);
    cudaGetSymbolAddress((void**)&We, g_we);
    cudaGetSymbolAddress((void**)&be, g_be);
    cudaGetSymbolAddress((void**)&bh, g_bh);
    cudaGetSymbolAddress((void**)&bl, g_bl);

    __nv_bfloat16* xh = (__nv_bfloat16*)xf;   // activation hi
    __nv_bfloat16* xl = (__nv_bfloat16*)x2f;  // activation lo

    cudaFuncSetAttribute(gemm_async<3>,
                         cudaFuncAttributeMaxDynamicSharedMemorySize, DSMEM_A);
    cudaFuncSetAttribute(gemm_async<2>,
                         cudaFuncAttributeMaxDynamicSharedMemorySize, DSMEM_A);

    // ---- prep: fold relations, then transpose+split all weights -----------
    wtrans_k<<<2 * LAY * 3 * NH, 256>>>(Wk, bk, Wv, bv, a_rel, m_rel, We, be);
    wsplit_k<<<768, 256>>>(W1, bh + WB_W1, bl + WB_W1, 768, 256);
    wsplit_all<<<6272, 256>>>(Wq, We, Wa, W2, bh, bl);

    // ---- input MLP: pair = split(lrelu(x @ W1 + b1))  (proven kernel) -----
    for (int t = 0; t < 3; t++) {
        dim3 grid(HID / 128, (Nn[t] + 127) / 128);
        gemm_mma<<<grid, 256>>>(xin[t], bh + WB_W1, bl + WB_W1, b1,
                                nullptr, nullptr, nullptr, nullptr,
                                xh + off[t] * HID, xl + off[t] * HID,
                                Nn[t], HID, INC, 0, 1, 2);
    }

    for (int l = 0; l < 2; l++) {
        // ---- Q projections (async<2>; only dst types review/user) ---------
        for (int t = 0; t < 3; t++) {
            if (t == 1) continue;
            size_t wo = WB_WQ + (size_t)(l * 3 + t) * 65536;
            dim3 grid(HID / 128, (Nn[t] + 127) / 128);
            gemm_async<2><<<grid, 256, DSMEM_A>>>(
                xh + off[t] * HID, xl + off[t] * HID, bh + wo, bl + wo,
                bq + (size_t)(l * 3 + t) * HID,
                (float*)((__half*)Qb + off[t] * HID), Nn[t], HID, 0, 1);
        }

        // ---- per-edge-type attention + aggregation ------------------------
        cudaMemsetAsync(ob, 0, ntot * HID * sizeof(float), 0);
        for (int e = 0; e < 3; e++) {
            int s = styp[e], t = dtyp[e];
            if (Es[e] <= 0) continue;

            size_t ik = WB_WE + (size_t)((0 * LAY + l) * 3 + e) * 65536;
            size_t iv = WB_WE + (size_t)((1 * LAY + l) * 3 + e) * 65536;
            size_t bik = (size_t)((0 * LAY + l) * 3 + e) * HID;
            size_t biv = (size_t)((1 * LAY + l) * 3 + e) * HID;
            dim3 grid(HID / 128, (Nn[s] + 127) / 128);
            gemm_async<2><<<grid, 256, DSMEM_A>>>(
                xh + off[s] * HID, xl + off[s] * HID, bh + ik, bl + ik,
                be + bik, kr, Nn[s], HID, 0, 1);
            gemm_async<3><<<grid, 256, DSMEM_A>>>(
                xh + off[s] * HID, xl + off[s] * HID, bh + iv, bl + iv,
                be + biv, vr, Nn[s], HID, 0, 1);

            cudaMemsetAsync(dn, 0, (size_t)Nn[t] * NH * sizeof(float), 0);

            logits_k<<<(Es[e] * 32 + 255) / 256, 256>>>(
                (const __half*)kr, (const __half*)Qb, srcs[e], dsts[e],
                p_rel + (size_t)(l * 3 + e) * NH, lg, dn, Es[e], (int)off[t]);
            msg_k<<<(Es[e] + 7) / 8, 256>>>((const __half*)vr, srcs[e], dsts[e],
                                            lg, dn, ob, Es[e], (int)off[t]);
        }

        // ---- output projection + gated skip (proven kernel, pair IO) ------
        for (int t = 0; t < 3; t++) {
            size_t wo = WB_WA + (size_t)(l * 3 + t) * 65536;
            dim3 grid(HID / 128, (Nn[t] + 127) / 128);
            gemm_mma<<<grid, 256>>>(ob + off[t] * HID, bh + wo, bl + wo,
                                    ba + (size_t)(l * 3 + t) * HID,
                                    xh + off[t] * HID, xl + off[t] * HID,
                                    skp + (l * 3 + t), nullptr,
                                    xh + off[t] * HID, xl + off[t] * HID,
                                    Nn[t], HID, HID, 1, 2, 2);
        }
    }

    // ---- final MLP (async<3>): lrelu(x @ W2 + b2), concatenated -----------
    float* outp = (float*)d_out;
    for (int t = 0; t < 3; t++) {
        dim3 grid(OUTC / 128, (Nn[t] + 127) / 128);
        gemm_async<3><<<grid, 256, DSMEM_A>>>(
            xh + off[t] * HID, xl + off[t] * HID, bh + WB_W2, bl + WB_W2,
            b2, outp + off[t] * OUTC, Nn[t], OUTC, 1, 0);
    }
}

// round 16
// speedup vs baseline: 1.5720x; 1.0562x over previous
#include <cuda_runtime.h>
#include <cuda_bf16.h>
#include <cuda_fp16.h>
#include <math.h>
#include <stdint.h>

// ---------------------------------------------------------------------------
// Problem constants
// ---------------------------------------------------------------------------
#define NH    8
#define DH    32
#define HID   256
#define INC   768
#define OUTC  128
#define NTOT  270000
#define NRMAX 200000
#define EMAX  200000
#define LAY   2

// ---------------------------------------------------------------------------
// Scratch (static device globals; allocation APIs forbidden). ~1.53 GB.
// ---------------------------------------------------------------------------
__device__ float g_x  [(size_t)NTOT * HID];   // used as bf16 hi activations
__device__ float g_x2 [(size_t)NTOT * HID];   // used as bf16 lo activations
__device__ float g_Q  [(size_t)NTOT * HID];   // used as __half
__device__ float g_o  [(size_t)NTOT * HID];   // used as __half attention accum
__device__ float g_kr [(size_t)NRMAX * HID];  // used as __half
__device__ float g_vr [(size_t)NRMAX * HID];  // used as __half
__device__ float g_lg [(size_t)EMAX * NH];
__device__ float g_dn [(size_t)NRMAX * NH];
// relation-folded K/V weights (fp32, [K][N])
__device__ float g_we [(size_t)2 * LAY * 3 * HID * HID];
__device__ float g_be [(size_t)2 * LAY * 3 * HID];
// all GEMM weights, transposed to [N][K], split into bf16 hi/lo
#define WB_W1 0
#define WB_WQ (WB_W1 + 256*768)
#define WB_WE (WB_WQ + 6*256*256)
#define WB_WA (WB_WE + 12*256*256)
#define WB_W2 (WB_WA + 6*256*256)
#define WB_TOT (WB_W2 + 128*256)
__device__ __nv_bfloat16 g_bh[WB_TOT];
__device__ __nv_bfloat16 g_bl[WB_TOT];

// ---------------------------------------------------------------------------
// Helpers
// ---------------------------------------------------------------------------
__device__ __forceinline__ uint32_t smem_u32(const void* p) {
    uint32_t a;
    asm("{ .reg .u64 t; cvta.to.shared.u64 t, %1; cvt.u32.u64 %0, t; }"
        : "=r"(a) : "l"(p));
    return a;
}
__device__ __forceinline__ float geluf(float v) {
    return 0.5f * v * (1.0f + erff(v * 0.70710678118654752f));
}

__device__ __forceinline__ void mma_bf16(float* c, const uint32_t* a,
                                         const uint32_t* b) {
    asm volatile(
        "mma.sync.aligned.m16n8k16.row.col.f32.bf16.bf16.f32 "
        "{%0,%1,%2,%3}, {%4,%5,%6,%7}, {%8,%9}, {%0,%1,%2,%3};\n"
        : "+f"(c[0]), "+f"(c[1]), "+f"(c[2]), "+f"(c[3])
        : "r"(a[0]), "r"(a[1]), "r"(a[2]), "r"(a[3]), "r"(b[0]), "r"(b[1]));
}
__device__ __forceinline__ void ldm_x4(uint32_t* r, uint32_t addr) {
    asm volatile("ldmatrix.sync.aligned.m8n8.x4.shared.b16 {%0,%1,%2,%3}, [%4];"
        : "=r"(r[0]), "=r"(r[1]), "=r"(r[2]), "=r"(r[3]) : "r"(addr));
}
__device__ __forceinline__ void ldm_x2(uint32_t* r, uint32_t addr) {
    asm volatile("ldmatrix.sync.aligned.m8n8.x2.shared.b16 {%0,%1}, [%2];"
        : "=r"(r[0]), "=r"(r[1]) : "r"(addr));
}
#define CP_ASYNC16P(dst, src, p) \
    asm volatile("cp.async.cg.shared.global [%0], [%1], 16, %2;" \
                 :: "r"(dst), "l"(src), "r"(p))
#define CP_COMMIT() asm volatile("cp.async.commit_group;" ::: "memory")
#define CP_WAIT1()  asm volatile("cp.async.wait_group 1;" ::: "memory")
#define CP_WAIT0()  asm volatile("cp.async.wait_group 0;" ::: "memory")

// ---------------------------------------------------------------------------
// Fold relation matrices into K/V projection weights (verified R3-R15)
// ---------------------------------------------------------------------------
__global__ __launch_bounds__(256)
void wtrans_k(const float* __restrict__ Wk, const float* __restrict__ bk,
              const float* __restrict__ Wv, const float* __restrict__ bv,
              const float* __restrict__ a_rel, const float* __restrict__ m_rel,
              float* __restrict__ We, float* __restrict__ be)
{
    const int styp[3] = { 1, 0, 2 };
    int idx = blockIdx.x;
    int h   = idx & 7;
    int e   = (idx >> 3) % 3;
    int l   = ((idx >> 3) / 3) % LAY;
    int kv  = idx / (8 * 3 * LAY);
    int s   = styp[e];

    const float* W = (kv == 0 ? Wk : Wv) + (size_t)(l * 3 + s) * HID * HID;
    const float* b = (kv == 0 ? bk : bv) + (size_t)(l * 3 + s) * HID;
    const float* A = (kv == 0 ? a_rel : m_rel)
                   + ((size_t)(l * 3 + e) * NH + h) * DH * DH;
    float* Wo = We + (size_t)((kv * LAY + l) * 3 + e) * HID * HID;
    float* bo = be + (size_t)((kv * LAY + l) * 3 + e) * HID;

    __shared__ float sA[DH][DH];
    if (threadIdx.x < DH * DH / 2) {
        int d = threadIdx.x >> 4, c = (threadIdx.x & 15) * 2;
        sA[d][c]     = A[d * DH + c];
        sA[d][c + 1] = A[d * DH + c + 1];
        sA[d + 16][c]     = A[(d + 16) * DH + c];
        sA[d + 16][c + 1] = A[(d + 16) * DH + c + 1];
    }
    __syncthreads();

    int i = threadIdx.x;
    float w[DH];
#pragma unroll
    for (int d = 0; d < DH; d++) w[d] = W[(size_t)i * HID + h * DH + d];
#pragma unroll 4
    for (int c = 0; c < DH; c++) {
        float acc = 0.0f;
#pragma unroll
        for (int d = 0; d < DH; d++) acc += w[d] * sA[d][c];
        Wo[(size_t)i * HID + h * DH + c] = acc;
    }
    if (i < DH) {
        float acc = 0.0f;
#pragma unroll
        for (int d = 0; d < DH; d++) acc += b[h * DH + d] * sA[d][i];
        bo[h * DH + i] = acc;
    }
}

// ---------------------------------------------------------------------------
// Transpose + split fp32 weight [K][N] -> bf16 hi/lo [N][K] (W1 only)
// ---------------------------------------------------------------------------
__global__ __launch_bounds__(256)
void wsplit_k(const float* __restrict__ src, __nv_bfloat16* __restrict__ hi,
              __nv_bfloat16* __restrict__ lo, int K, int N)
{
    int i = blockIdx.x * 256 + threadIdx.x;
    if (i >= K * N) return;
    int n = i / K, k = i - n * K;
    float w = src[(size_t)k * N + n];
    __nv_bfloat16 h = __float2bfloat16(w);
    hi[i] = h;
    lo[i] = __float2bfloat16(w - __bfloat162float(h));
}

// ---------------------------------------------------------------------------
// Batched transpose+split for all K=256 weights: Wq(6) We(12) Wa(6) W2(1).
// ---------------------------------------------------------------------------
__global__ __launch_bounds__(256)
void wsplit_all(const float* __restrict__ Wq, const float* __restrict__ We,
                const float* __restrict__ Wa, const float* __restrict__ W2,
                __nv_bfloat16* __restrict__ bh, __nv_bfloat16* __restrict__ bl)
{
    int bid = blockIdx.x;
    const float* src;
    size_t off;
    int N, inner;
    if (bid < 6144) {
        int seg = bid >> 8;
        inner = ((bid & 255) << 8) | threadIdx.x;
        N = 256;
        if (seg < 6)       { src = Wq + (size_t)seg * 65536;        off = WB_WQ + (size_t)seg * 65536; }
        else if (seg < 18) { src = We + (size_t)(seg - 6) * 65536;  off = WB_WE + (size_t)(seg - 6) * 65536; }
        else               { src = Wa + (size_t)(seg - 18) * 65536; off = WB_WA + (size_t)(seg - 18) * 65536; }
    } else {
        inner = ((bid - 6144) << 8) | threadIdx.x;
        N = 128; src = W2; off = WB_W2;
    }
    int n = inner >> 8;
    int k = inner & 255;
    float w = src[(size_t)k * N + n];
    __nv_bfloat16 h = __float2bfloat16(w);
    bh[off + inner] = h;
    bl[off + inner] = __float2bfloat16(w - __bfloat162float(h));
}

#define LDS 40   // smem row stride in halves (80B: conflict-free ldmatrix)

// ---------------------------------------------------------------------------
// Proven convert-GEMM (mainloop verbatim from R13/R15, 2 CTA/SM), templated:
// AH=0: A fp32; AH=1: A __half (fp16->bf16-pair split is exact).
// outmode: 0 = fp32 C, 1 = __half C, 2 = bf16 hi/lo pair (Ch, Cl)
// epi=2 reads skip input from bf16 pair (Xh, Xl).
// ---------------------------------------------------------------------------
template <int AH>
__global__ __launch_bounds__(256)
void gemm_mma(const void* __restrict__ Avoid,
              const __nv_bfloat16* __restrict__ Bh,
              const __nv_bfloat16* __restrict__ Bl,
              const float* __restrict__ bias,
              const __nv_bfloat16* __restrict__ Xh,
              const __nv_bfloat16* __restrict__ Xl,
              const float* __restrict__ skipp, float* __restrict__ C,
              __nv_bfloat16* __restrict__ Ch, __nv_bfloat16* __restrict__ Cl,
              int M, int N, int K, int actA, int epi, int outmode)
{
    __shared__ __align__(16) __nv_bfloat16 sAh[128 * LDS];
    __shared__ __align__(16) __nv_bfloat16 sAl[128 * LDS];
    __shared__ __align__(16) __nv_bfloat16 sBh[128 * LDS];
    __shared__ __align__(16) __nv_bfloat16 sBl[128 * LDS];

    const int tid  = threadIdx.x;
    const int wid  = tid >> 5;
    const int lane = tid & 31;
    const int wm   = wid >> 2;
    const int wn   = wid & 3;
    const int row0 = blockIdx.y * 128;
    const int col0 = blockIdx.x * 128;

    const int lrow = tid >> 1;
    const int lk   = (tid & 1) * 16;
    const int aGR  = row0 + lrow;
    const bool av  = (aGR < M);
    const __nv_bfloat16* BHrow = Bh + (size_t)(col0 + lrow) * K;
    const __nv_bfloat16* BLrow = Bl + (size_t)(col0 + lrow) * K;

    const int a_r = (lane & 7) + ((lane >> 3) & 1) * 8;
    const int a_c = ((lane >> 4) & 1) * 8;
    const int b_r = (lane & 7);
    const int b_c = ((lane >> 3) & 1) * 8;

    const uint32_t uAh = smem_u32(sAh), uAl = smem_u32(sAl);
    const uint32_t uBh = smem_u32(sBh), uBl = smem_u32(sBl);
    const uint32_t aoff = (uint32_t)((wm * 64 + a_r) * LDS + a_c) * 2;
    const uint32_t boff = (uint32_t)((wn * 32 + b_r) * LDS + b_c) * 2;
    const uint32_t sto  = (uint32_t)(lrow * LDS + lk);

    float acc[4][4][4];
#pragma unroll
    for (int i = 0; i < 4; i++)
#pragma unroll
        for (int j = 0; j < 4; j++)
#pragma unroll
            for (int r = 0; r < 4; r++) acc[i][j][r] = 0.0f;

    const int NC = K / 32;
    for (int c = 0; c < NC; c++) {
        const int kb = c * 32 + lk;

        float4 f0, f1, f2, f3;
        if (AH == 0) {
            const float* Arow = (const float*)Avoid + (size_t)aGR * K;
            if (av) {
                f0 = *(const float4*)(Arow + kb);
                f1 = *(const float4*)(Arow + kb + 4);
                f2 = *(const float4*)(Arow + kb + 8);
                f3 = *(const float4*)(Arow + kb + 12);
            } else {
                f0 = make_float4(0.f, 0.f, 0.f, 0.f); f1 = f0; f2 = f0; f3 = f0;
            }
        } else {
            const __half* Arow = (const __half*)Avoid + (size_t)aGR * K;
            uint4 p0, p1;
            if (av) {
                p0 = *(const uint4*)(Arow + kb);
                p1 = *(const uint4*)(Arow + kb + 8);
            } else {
                p0 = make_uint4(0u, 0u, 0u, 0u); p1 = p0;
            }
            const __half2* q = (const __half2*)&p0;
            float2 a0 = __half22float2(q[0]), a1 = __half22float2(q[1]);
            float2 a2 = __half22float2(q[2]), a3 = __half22float2(q[3]);
            const __half2* r = (const __half2*)&p1;
            float2 a4 = __half22float2(r[0]), a5 = __half22float2(r[1]);
            float2 a6 = __half22float2(r[2]), a7 = __half22float2(r[3]);
            f0 = make_float4(a0.x, a0.y, a1.x, a1.y);
            f1 = make_float4(a2.x, a2.y, a3.x, a3.y);
            f2 = make_float4(a4.x, a4.y, a5.x, a5.y);
            f3 = make_float4(a6.x, a6.y, a7.x, a7.y);
        }
        if (actA) {
            f0.x = geluf(f0.x); f0.y = geluf(f0.y); f0.z = geluf(f0.z); f0.w = geluf(f0.w);
            f1.x = geluf(f1.x); f1.y = geluf(f1.y); f1.z = geluf(f1.z); f1.w = geluf(f1.w);
            f2.x = geluf(f2.x); f2.y = geluf(f2.y); f2.z = geluf(f2.z); f2.w = geluf(f2.w);
            f3.x = geluf(f3.x); f3.y = geluf(f3.y); f3.z = geluf(f3.z); f3.w = geluf(f3.w);
        }
        uint4 bh0 = *(const uint4*)(BHrow + kb);
        uint4 bh1 = *(const uint4*)(BHrow + kb + 8);
        uint4 bl0 = *(const uint4*)(BLrow + kb);
        uint4 bl1 = *(const uint4*)(BLrow + kb + 8);

        if (c) __syncthreads();

        __nv_bfloat162 h0 = __floats2bfloat162_rn(f0.x, f0.y);
        __nv_bfloat162 h1 = __floats2bfloat162_rn(f0.z, f0.w);
        __nv_bfloat162 h2 = __floats2bfloat162_rn(f1.x, f1.y);
        __nv_bfloat162 h3 = __floats2bfloat162_rn(f1.z, f1.w);
        __nv_bfloat162 h4 = __floats2bfloat162_rn(f2.x, f2.y);
        __nv_bfloat162 h5 = __floats2bfloat162_rn(f2.z, f2.w);
        __nv_bfloat162 h6 = __floats2bfloat162_rn(f3.x, f3.y);
        __nv_bfloat162 h7 = __floats2bfloat162_rn(f3.z, f3.w);
        __nv_bfloat162 l0 = __floats2bfloat162_rn(f0.x - __bfloat162float(h0.x), f0.y - __bfloat162float(h0.y));
        __nv_bfloat162 l1 = __floats2bfloat162_rn(f0.z - __bfloat162float(h1.x), f0.w - __bfloat162float(h1.y));
        __nv_bfloat162 l2 = __floats2bfloat162_rn(f1.x - __bfloat162float(h2.x), f1.y - __bfloat162float(h2.y));
        __nv_bfloat162 l3 = __floats2bfloat162_rn(f1.z - __bfloat162float(h3.x), f1.w - __bfloat162float(h3.y));
        __nv_bfloat162 l4 = __floats2bfloat162_rn(f2.x - __bfloat162float(h4.x), f2.y - __bfloat162float(h4.y));
        __nv_bfloat162 l5 = __floats2bfloat162_rn(f2.z - __bfloat162float(h5.x), f2.w - __bfloat162float(h5.y));
        __nv_bfloat162 l6 = __floats2bfloat162_rn(f3.x - __bfloat162float(h6.x), f3.y - __bfloat162float(h6.y));
        __nv_bfloat162 l7 = __floats2bfloat162_rn(f3.z - __bfloat162float(h7.x), f3.w - __bfloat162float(h7.y));
        *(uint4*)&sAh[sto]     = make_uint4(*(uint32_t*)&h0, *(uint32_t*)&h1, *(uint32_t*)&h2, *(uint32_t*)&h3);
        *(uint4*)&sAh[sto + 8] = make_uint4(*(uint32_t*)&h4, *(uint32_t*)&h5, *(uint32_t*)&h6, *(uint32_t*)&h7);
        *(uint4*)&sAl[sto]     = make_uint4(*(uint32_t*)&l0, *(uint32_t*)&l1, *(uint32_t*)&l2, *(uint32_t*)&l3);
        *(uint4*)&sAl[sto + 8] = make_uint4(*(uint32_t*)&l4, *(uint32_t*)&l5, *(uint32_t*)&l6, *(uint32_t*)&l7);
        *(uint4*)&sBh[sto]     = bh0;
        *(uint4*)&sBh[sto + 8] = bh1;
        *(uint4*)&sBl[sto]     = bl0;
        *(uint4*)&sBl[sto + 8] = bl1;
        __syncthreads();

#pragma unroll
        for (int ks = 0; ks < 2; ks++) {
            const uint32_t kof = (uint32_t)(ks * 16) * 2;
            uint32_t ah[4][4], al[4][4];
#pragma unroll
            for (int i = 0; i < 4; i++) {
                uint32_t ro = (uint32_t)(i * 16 * LDS) * 2;
                ldm_x4(ah[i], uAh + aoff + ro + kof);
                ldm_x4(al[i], uAl + aoff + ro + kof);
            }
            uint32_t bhf[4][2], blf[4][2];
#pragma unroll
            for (int j = 0; j < 4; j++) {
                uint32_t ro = (uint32_t)(j * 8 * LDS) * 2;
                ldm_x2(bhf[j], uBh + boff + ro + kof);
                ldm_x2(blf[j], uBl + boff + ro + kof);
            }
#pragma unroll
            for (int i = 0; i < 4; i++)
#pragma unroll
                for (int j = 0; j < 4; j++) {
                    mma_bf16(acc[i][j], ah[i], bhf[j]);
                    mma_bf16(acc[i][j], ah[i], blf[j]);
                    mma_bf16(acc[i][j], al[i], bhf[j]);
                }
        }
    }

    float g = 0.0f;
    if (epi == 2) g = 1.0f / (1.0f + expf(-skipp[0]));

#pragma unroll
    for (int i = 0; i < 4; i++) {
#pragma unroll
        for (int half = 0; half < 2; half++) {
            int m = row0 + wm * 64 + i * 16 + (lane >> 2) + half * 8;
            if (m >= M) continue;
            size_t rb = (size_t)m * N;
#pragma unroll
            for (int j = 0; j < 4; j++) {
                int n = col0 + wn * 32 + j * 8 + (lane & 3) * 2;
                float v0 = acc[i][j][half * 2 + 0] + bias[n];
                float v1 = acc[i][j][half * 2 + 1] + bias[n + 1];
                if (epi == 1) {
                    v0 = (v0 > 0.f) ? v0 : 0.01f * v0;
                    v1 = (v1 > 0.f) ? v1 : 0.01f * v1;
                } else if (epi == 2) {
                    __nv_bfloat162 xh2 = *(const __nv_bfloat162*)(Xh + rb + n);
                    __nv_bfloat162 xl2 = *(const __nv_bfloat162*)(Xl + rb + n);
                    float x0 = __bfloat162float(xh2.x) + __bfloat162float(xl2.x);
                    float x1 = __bfloat162float(xh2.y) + __bfloat162float(xl2.y);
                    v0 = g * v0 + (1.f - g) * x0;
                    v1 = g * v1 + (1.f - g) * x1;
                }
                if (outmode == 2) {
                    __nv_bfloat16 ch0 = __float2bfloat16(v0);
                    __nv_bfloat16 ch1 = __float2bfloat16(v1);
                    __nv_bfloat162 co; co.x = ch0; co.y = ch1;
                    *(__nv_bfloat162*)(Ch + rb + n) = co;
                    __nv_bfloat162 cl;
                    cl.x = __float2bfloat16(v0 - __bfloat162float(ch0));
                    cl.y = __float2bfloat16(v1 - __bfloat162float(ch1));
                    *(__nv_bfloat162*)(Cl + rb + n) = cl;
                } else if (outmode == 1) {
                    *(__half2*)((__half*)C + rb + n) = __floats2half2_rn(v0, v1);
                } else {
                    float2 o; o.x = v0; o.y = v1;
                    *(float2*)(C + rb + n) = o;
                }
            }
        }
    }
}

// ---------------------------------------------------------------------------
// Async GEMM (templated on NTERMS): A pre-split bf16 hi/lo [M][256].
// 2-stage cp.async pipeline, K fixed at 256. Last-chunk wait0 (exact).
// ---------------------------------------------------------------------------
#define ATILE (128 * LDS)         // halves per tile (5120)
#define ASTG  (4 * ATILE)         // halves per stage (20480)
#define DSMEM_A (2 * ASTG * 2)    // bytes (81920)

template <int NTERMS>
__global__ __launch_bounds__(256)
void gemm_async(const __nv_bfloat16* __restrict__ Ah,
                const __nv_bfloat16* __restrict__ Al,
                const __nv_bfloat16* __restrict__ Bh,
                const __nv_bfloat16* __restrict__ Bl,
                const float* __restrict__ bias, float* __restrict__ C,
                int M, int N, int epi, int outmode)
{
    extern __shared__ __align__(16) __nv_bfloat16 sm[];
    const uint32_t smb = smem_u32(sm);

    const int tid  = threadIdx.x;
    const int wid  = tid >> 5;
    const int lane = tid & 31;
    const int wm   = wid >> 2;
    const int wn   = wid & 3;
    const int row0 = blockIdx.y * 128;
    const int col0 = blockIdx.x * 128;
    const int K = 256;

    const int a_r = (lane & 7) + ((lane >> 3) & 1) * 8;
    const int a_c = ((lane >> 4) & 1) * 8;
    const int b_r = (lane & 7);
    const int b_c = ((lane >> 3) & 1) * 8;
    const uint32_t aoff = (uint32_t)((wm * 64 + a_r) * LDS + a_c) * 2;
    const uint32_t boff = (uint32_t)((wn * 32 + b_r) * LDS + b_c) * 2;

    float acc[4][4][4];
#pragma unroll
    for (int i = 0; i < 4; i++)
#pragma unroll
        for (int j = 0; j < 4; j++)
#pragma unroll
            for (int r = 0; r < 4; r++) acc[i][j][r] = 0.0f;

    const int NC = 8;

    auto issue = [&](int stage, int chunk) {
        const int kb = chunk * 32;
#pragma unroll
        for (int i = 0; i < 2; i++) {
            int cid = tid + i * 256;
            int row = cid >> 2;
            int seg = cid & 3;
            uint32_t dst = smb + (uint32_t)(stage * ASTG + row * LDS + seg * 8) * 2;
            const int ga = row0 + row;
            uint32_t pa = (ga < M) ? 16u : 0u;
            const __nv_bfloat16* sa = Ah + (size_t)ga * K + kb + seg * 8;
            const __nv_bfloat16* sl = Al + (size_t)ga * K + kb + seg * 8;
            const __nv_bfloat16* sb = Bh + (size_t)(col0 + row) * K + kb + seg * 8;
            const __nv_bfloat16* sc = Bl + (size_t)(col0 + row) * K + kb + seg * 8;
            CP_ASYNC16P(dst,                 sa, pa);
            CP_ASYNC16P(dst + ATILE * 2,     sl, pa);
            CP_ASYNC16P(dst + 2 * ATILE * 2, sb, 16u);
            CP_ASYNC16P(dst + 3 * ATILE * 2, sc, 16u);
        }
        CP_COMMIT();
    };

    issue(0, 0);
    issue(1, 1);

    for (int c = 0; c < NC; c++) {
        const int st = c & 1;
        if (c >= NC - 1) CP_WAIT0(); else CP_WAIT1();
        __syncthreads();

        const uint32_t base = smb + (uint32_t)(st * ASTG) * 2;
        const uint32_t uAh = base;
        const uint32_t uAl = base + ATILE * 2;
        const uint32_t uBh = base + 2 * ATILE * 2;
        const uint32_t uBl = base + 3 * ATILE * 2;
#pragma unroll
        for (int ks = 0; ks < 2; ks++) {
            const uint32_t kof = (uint32_t)(ks * 16) * 2;
            uint32_t ah[4][4], al[4][4];
#pragma unroll
            for (int i = 0; i < 4; i++) {
                uint32_t ro = (uint32_t)(i * 16 * LDS) * 2;
                ldm_x4(ah[i], uAh + aoff + ro + kof);
                if (NTERMS == 3) ldm_x4(al[i], uAl + aoff + ro + kof);
            }
            uint32_t bhf[4][2], blf[4][2];
#pragma unroll
            for (int j = 0; j < 4; j++) {
                uint32_t ro = (uint32_t)(j * 8 * LDS) * 2;
                ldm_x2(bhf[j], uBh + boff + ro + kof);
                ldm_x2(blf[j], uBl + boff + ro + kof);
            }
#pragma unroll
            for (int i = 0; i < 4; i++)
#pragma unroll
                for (int j = 0; j < 4; j++) {
                    mma_bf16(acc[i][j], ah[i], bhf[j]);
                    mma_bf16(acc[i][j], ah[i], blf[j]);
                    if (NTERMS == 3) mma_bf16(acc[i][j], al[i], bhf[j]);
                }
        }
        __syncthreads();
        if (c + 2 < NC) issue(st, c + 2);
    }

    // ---- epilogue ----
#pragma unroll
    for (int i = 0; i < 4; i++) {
#pragma unroll
        for (int half = 0; half < 2; half++) {
            int m = row0 + wm * 64 + i * 16 + (lane >> 2) + half * 8;
            if (m >= M) continue;
            size_t rb = (size_t)m * N;
#pragma unroll
            for (int j = 0; j < 4; j++) {
                int n = col0 + wn * 32 + j * 8 + (lane & 3) * 2;
                float v0 = acc[i][j][half * 2 + 0] + bias[n];
                float v1 = acc[i][j][half * 2 + 1] + bias[n + 1];
                if (epi == 1) {
                    v0 = (v0 > 0.f) ? v0 : 0.01f * v0;
                    v1 = (v1 > 0.f) ? v1 : 0.01f * v1;
                }
                if (outmode == 1) {
                    *(__half2*)((__half*)C + rb + n) = __floats2half2_rn(v0, v1);
                } else {
                    float2 o; o.x = v0; o.y = v1;
                    *(float2*)(C + rb + n) = o;
                }
            }
        }
    }
}

// ---------------------------------------------------------------------------
// Fused edge logits + exp + denominator (fp16 KR/Q, verified R10-R15).
// ---------------------------------------------------------------------------
__global__ __launch_bounds__(256)
void logits_k(const __half* __restrict__ KR, const __half* __restrict__ Q,
              const int* __restrict__ src, const int* __restrict__ dst,
              const float* __restrict__ prel, float* __restrict__ expv,
              float* __restrict__ den, int E, int dst_off)
{
    int w    = (blockIdx.x * 256 + threadIdx.x) >> 5;
    int lane = threadIdx.x & 31;
    if (w >= E) return;
    int r = src[w], c = dst[w];
    const __half* kp = KR + (size_t)r * HID;
    const __half* qp = Q + (size_t)(dst_off + c) * HID;
    const float inv = 0.17677669529663687f;

    uint4 kv = *(const uint4*)(kp + lane * 8);
    uint4 qv = *(const uint4*)(qp + lane * 8);
    const __half2* k2 = (const __half2*)&kv;
    const __half2* q2 = (const __half2*)&qv;
    float v = 0.0f;
#pragma unroll
    for (int i = 0; i < 4; i++) {
        float2 a = __half22float2(k2[i]);
        float2 b = __half22float2(q2[i]);
        v += a.x * b.x + a.y * b.y;
    }
    v += __shfl_down_sync(0xffffffffu, v, 2);
    v += __shfl_down_sync(0xffffffffu, v, 1);
    if ((lane & 3) == 0) {
        int h = lane >> 2;
        float ex = expf(v * prel[h] * inv);
        expv[(size_t)w * NH + h] = ex;
        atomicAdd(&den[(size_t)c * NH + h], ex);
    }
}

// ---------------------------------------------------------------------------
// Message scatter (fp16 VR, fp16 OUT): out[dst, :] += vr[src, :] * attn.
// Warp per edge; lane covers 8 halves; single red.global.add.noftz.v4.f16x2.
// ---------------------------------------------------------------------------
__global__ __launch_bounds__(256)
void msg_k(const __half* __restrict__ VR, const int* __restrict__ src,
           const int* __restrict__ dst, const float* __restrict__ exv,
           const float* __restrict__ den, __half* __restrict__ out,
           int E, int dst_off)
{
    int eid = blockIdx.x * 8 + (threadIdx.x >> 5);
    if (eid >= E) return;
    int j = threadIdx.x & 31;          // covers halves [8j, 8j+8)
    int h = j >> 2;                    // 4 lanes per 32-wide head
    int r = src[eid], c = dst[eid];
    float attn = exv[(size_t)eid * NH + h] / (den[(size_t)c * NH + h] + 1e-16f);
    uint4 v = *(const uint4*)(VR + (size_t)r * HID + j * 8);
    __half2 a2 = __float2half2_rn(attn);
    __half2 m0 = __hmul2(((const __half2*)&v)[0], a2);
    __half2 m1 = __hmul2(((const __half2*)&v)[1], a2);
    __half2 m2 = __hmul2(((const __half2*)&v)[2], a2);
    __half2 m3 = __hmul2(((const __half2*)&v)[3], a2);
    __half* dp = out + (size_t)(dst_off + c) * HID + j * 8;
    asm volatile("red.global.add.noftz.v4.f16x2 [%0], {%1,%2,%3,%4};"
                 :: "l"(dp), "r"(*(uint32_t*)&m0), "r"(*(uint32_t*)&m1),
                    "r"(*(uint32_t*)&m2), "r"(*(uint32_t*)&m3)
                 : "memory");
}

// ---------------------------------------------------------------------------
// Host orchestration
// ---------------------------------------------------------------------------
extern "C" void kernel_launch(void* const* d_in, const int* in_sizes, int n_in,
                              void* d_out, int out_size)
{
    (void)n_in; (void)out_size;

    const float* xin[3] = { (const float*)d_in[0], (const float*)d_in[1],
                            (const float*)d_in[2] };
    const int* srcs[3] = { (const int*)d_in[3], (const int*)d_in[5], (const int*)d_in[7] };
    const int* dsts[3] = { (const int*)d_in[4], (const int*)d_in[6], (const int*)d_in[8] };
    int Es[3]   = { in_sizes[3], in_sizes[5], in_sizes[7] };
    int styp[3] = { 1, 0, 2 };
    int dtyp[3] = { 2, 2, 0 };

    int Nn[3] = { in_sizes[0] / INC, in_sizes[1] / INC, in_sizes[2] / INC };
    size_t off[3] = { 0, (size_t)Nn[0], (size_t)Nn[0] + (size_t)Nn[1] };
    size_t ntot = off[2] + (size_t)Nn[2];

    const float* W1    = (const float*)d_in[9];
    const float* b1    = (const float*)d_in[10];
    const float* W2    = (const float*)d_in[11];
    const float* b2    = (const float*)d_in[12];
    const float* Wk    = (const float*)d_in[13];
    const float* bk    = (const float*)d_in[14];
    const float* Wq    = (const float*)d_in[15];
    const float* bq    = (const float*)d_in[16];
    const float* Wv    = (const float*)d_in[17];
    const float* bv    = (const float*)d_in[18];
    const float* Wa    = (const float*)d_in[19];
    const float* ba    = (const float*)d_in[20];
    const float* skp   = (const float*)d_in[21];
    const float* a_rel = (const float*)d_in[22];
    const float* m_rel = (const float*)d_in[23];
    const float* p_rel = (const float*)d_in[24];

    float *xf, *x2f, *Qb, *ob, *kr, *vr, *lg, *dn, *We, *be;
    __nv_bfloat16 *bh, *bl;
    cudaGetSymbolAddress((void**)&xf,  g_x);
    cudaGetSymbolAddress((void**)&x2f, g_x2);
    cudaGetSymbolAddress((void**)&Qb, g_Q);
    cudaGetSymbolAddress((void**)&ob, g_o);
    cudaGetSymbolAddress((void**)&kr, g_kr);
    cudaGetSymbolAddress((void**)&vr, g_vr);
    cudaGetSymbolAddress((void**)&lg, g_lg);
    cudaGetSymbolAddress((void**)&dn, g_dn);
    cudaGetSymbolAddress((void**)&We, g_we);
    cudaGetSymbolAddress((void**)&be, g_be);
    cudaGetSymbolAddress((void**)&bh, g_bh);
    cudaGetSymbolAddress((void**)&bl, g_bl);

    __nv_bfloat16* xh = (__nv_bfloat16*)xf;   // activation hi
    __nv_bfloat16* xl = (__nv_bfloat16*)x2f;  // activation lo
    __half* obh = (__half*)ob;                // fp16 attention accumulator

    cudaFuncSetAttribute(gemm_async<3>,
                         cudaFuncAttributeMaxDynamicSharedMemorySize, DSMEM_A);
    cudaFuncSetAttribute(gemm_async<2>,
                         cudaFuncAttributeMaxDynamicSharedMemorySize, DSMEM_A);

    // ---- prep: fold relations, then transpose+split all weights -----------
    wtrans_k<<<2 * LAY * 3 * NH, 256>>>(Wk, bk, Wv, bv, a_rel, m_rel, We, be);
    wsplit_k<<<768, 256>>>(W1, bh + WB_W1, bl + WB_W1, 768, 256);
    wsplit_all<<<6272, 256>>>(Wq, We, Wa, W2, bh, bl);

    // ---- input MLP: pair = split(lrelu(x @ W1 + b1))  (proven kernel) -----
    for (int t = 0; t < 3; t++) {
        dim3 grid(HID / 128, (Nn[t] + 127) / 128);
        gemm_mma<0><<<grid, 256>>>(xin[t], bh + WB_W1, bl + WB_W1, b1,
                                   nullptr, nullptr, nullptr, nullptr,
                                   xh + off[t] * HID, xl + off[t] * HID,
                                   Nn[t], HID, INC, 0, 1, 2);
    }

    for (int l = 0; l < 2; l++) {
        // ---- Q projections (async<2>; only dst types review/user) ---------
        for (int t = 0; t < 3; t++) {
            if (t == 1) continue;
            size_t wo = WB_WQ + (size_t)(l * 3 + t) * 65536;
            dim3 grid(HID / 128, (Nn[t] + 127) / 128);
            gemm_async<2><<<grid, 256, DSMEM_A>>>(
                xh + off[t] * HID, xl + off[t] * HID, bh + wo, bl + wo,
                bq + (size_t)(l * 3 + t) * HID,
                (float*)((__half*)Qb + off[t] * HID), Nn[t], HID, 0, 1);
        }

        // ---- per-edge-type attention + aggregation ------------------------
        cudaMemsetAsync(obh, 0, ntot * HID * sizeof(__half), 0);
        for (int e = 0; e < 3; e++) {
            int s = styp[e], t = dtyp[e];
            if (Es[e] <= 0) continue;

            size_t ik = WB_WE + (size_t)((0 * LAY + l) * 3 + e) * 65536;
            size_t iv = WB_WE + (size_t)((1 * LAY + l) * 3 + e) * 65536;
            size_t bik = (size_t)((0 * LAY + l) * 3 + e) * HID;
            size_t biv = (size_t)((1 * LAY + l) * 3 + e) * HID;
            dim3 grid(HID / 128, (Nn[s] + 127) / 128);
            gemm_async<2><<<grid, 256, DSMEM_A>>>(
                xh + off[s] * HID, xl + off[s] * HID, bh + ik, bl + ik,
                be + bik, kr, Nn[s], HID, 0, 1);
            gemm_async<3><<<grid, 256, DSMEM_A>>>(
                xh + off[s] * HID, xl + off[s] * HID, bh + iv, bl + iv,
                be + biv, vr, Nn[s], HID, 0, 1);

            cudaMemsetAsync(dn, 0, (size_t)Nn[t] * NH * sizeof(float), 0);

            logits_k<<<(Es[e] * 32 + 255) / 256, 256>>>(
                (const __half*)kr, (const __half*)Qb, srcs[e], dsts[e],
                p_rel + (size_t)(l * 3 + e) * NH, lg, dn, Es[e], (int)off[t]);
            msg_k<<<(Es[e] + 7) / 8, 256>>>((const __half*)vr, srcs[e], dsts[e],
                                            lg, dn, obh, Es[e], (int)off[t]);
        }

        // ---- output projection + gated skip (proven kernel, fp16 A) -------
        for (int t = 0; t < 3; t++) {
            size_t wo = WB_WA + (size_t)(l * 3 + t) * 65536;
            dim3 grid(HID / 128, (Nn[t] + 127) / 128);
            gemm_mma<1><<<grid, 256>>>(obh + off[t] * HID, bh + wo, bl + wo,
                                       ba + (size_t)(l * 3 + t) * HID,
                                       xh + off[t] * HID, xl + off[t] * HID,
                                       skp + (l * 3 + t), nullptr,
                                       xh + off[t] * HID, xl + off[t] * HID,
                                       Nn[t], HID, HID, 1, 2, 2);
        }
    }

    // ---- final MLP (async<3>): lrelu(x @ W2 + b2), concatenated -----------
    float* outp = (float*)d_out;
    for (int t = 0; t < 3; t++) {
        dim3 grid(OUTC / 128, (Nn[t] + 127) / 128);
        gemm_async<3><<<grid, 256, DSMEM_A>>>(
            xh + off[t] * HID, xl + off[t] * HID, bh + WB_W2, bl + WB_W2,
            b2, outp + off[t] * OUTC, Nn[t], OUTC, 1, 0);
    }
}

// round 17
// speedup vs baseline: 1.9375x; 1.2325x over previous
#include <cuda_runtime.h>
#include <cuda_bf16.h>
#include <cuda_fp16.h>
#include <math.h>
#include <stdint.h>

// ---------------------------------------------------------------------------
// Problem constants
// ---------------------------------------------------------------------------
#define NH    8
#define DH    32
#define HID   256
#define INC   768
#define OUTC  128
#define NTOT  270000
#define NRMAX 200000
#define EMAX  200000
#define LAY   2

// ---------------------------------------------------------------------------
// Scratch (static device globals; allocation APIs forbidden). ~1.53 GB.
// ---------------------------------------------------------------------------
__device__ float g_x  [(size_t)NTOT * HID];   // used as bf16 hi activations
__device__ float g_x2 [(size_t)NTOT * HID];   // used as bf16 lo activations
__device__ float g_Q  [(size_t)NTOT * HID];   // used as __half
__device__ float g_o  [(size_t)NTOT * HID];   // used as __half attention accum
__device__ float g_kr [(size_t)NRMAX * HID];  // used as __half
__device__ float g_vr [(size_t)NRMAX * HID];  // used as __half
__device__ float g_lg [(size_t)EMAX * NH];
__device__ float g_dn [(size_t)NRMAX * NH];
// relation-folded K/V weights (fp32, [K][N])
__device__ float g_we [(size_t)2 * LAY * 3 * HID * HID];
__device__ float g_be [(size_t)2 * LAY * 3 * HID];
// all GEMM weights, transposed to [N][K], split into bf16 hi/lo
#define WB_W1 0
#define WB_WQ (WB_W1 + 256*768)
#define WB_WE (WB_WQ + 6*256*256)
#define WB_WA (WB_WE + 12*256*256)
#define WB_W2 (WB_WA + 6*256*256)
#define WB_TOT (WB_W2 + 128*256)
__device__ __nv_bfloat16 g_bh[WB_TOT];
__device__ __nv_bfloat16 g_bl[WB_TOT];

// ---------------------------------------------------------------------------
// Helpers
// ---------------------------------------------------------------------------
__device__ __forceinline__ uint32_t smem_u32(const void* p) {
    uint32_t a;
    asm("{ .reg .u64 t; cvta.to.shared.u64 t, %1; cvt.u32.u64 %0, t; }"
        : "=r"(a) : "l"(p));
    return a;
}
__device__ __forceinline__ float geluf(float v) {
    return 0.5f * v * (1.0f + erff(v * 0.70710678118654752f));
}

__device__ __forceinline__ void mma_bf16(float* c, const uint32_t* a,
                                         const uint32_t* b) {
    asm volatile(
        "mma.sync.aligned.m16n8k16.row.col.f32.bf16.bf16.f32 "
        "{%0,%1,%2,%3}, {%4,%5,%6,%7}, {%8,%9}, {%0,%1,%2,%3};\n"
        : "+f"(c[0]), "+f"(c[1]), "+f"(c[2]), "+f"(c[3])
        : "r"(a[0]), "r"(a[1]), "r"(a[2]), "r"(a[3]), "r"(b[0]), "r"(b[1]));
}
__device__ __forceinline__ void ldm_x4(uint32_t* r, uint32_t addr) {
    asm volatile("ldmatrix.sync.aligned.m8n8.x4.shared.b16 {%0,%1,%2,%3}, [%4];"
        : "=r"(r[0]), "=r"(r[1]), "=r"(r[2]), "=r"(r[3]) : "r"(addr));
}
__device__ __forceinline__ void ldm_x2(uint32_t* r, uint32_t addr) {
    asm volatile("ldmatrix.sync.aligned.m8n8.x2.shared.b16 {%0,%1}, [%2];"
        : "=r"(r[0]), "=r"(r[1]) : "r"(addr));
}
#define CP_ASYNC16P(dst, src, p) \
    asm volatile("cp.async.cg.shared.global [%0], [%1], 16, %2;" \
                 :: "r"(dst), "l"(src), "r"(p))
#define CP_COMMIT() asm volatile("cp.async.commit_group;" ::: "memory")
#define CP_WAIT1()  asm volatile("cp.async.wait_group 1;" ::: "memory")
#define CP_WAIT0()  asm volatile("cp.async.wait_group 0;" ::: "memory")

// ---------------------------------------------------------------------------
// Fold relation matrices into K/V projection weights (verified R3-R16)
// ---------------------------------------------------------------------------
__global__ __launch_bounds__(256)
void wtrans_k(const float* __restrict__ Wk, const float* __restrict__ bk,
              const float* __restrict__ Wv, const float* __restrict__ bv,
              const float* __restrict__ a_rel, const float* __restrict__ m_rel,
              float* __restrict__ We, float* __restrict__ be)
{
    const int styp[3] = { 1, 0, 2 };
    int idx = blockIdx.x;
    int h   = idx & 7;
    int e   = (idx >> 3) % 3;
    int l   = ((idx >> 3) / 3) % LAY;
    int kv  = idx / (8 * 3 * LAY);
    int s   = styp[e];

    const float* W = (kv == 0 ? Wk : Wv) + (size_t)(l * 3 + s) * HID * HID;
    const float* b = (kv == 0 ? bk : bv) + (size_t)(l * 3 + s) * HID;
    const float* A = (kv == 0 ? a_rel : m_rel)
                   + ((size_t)(l * 3 + e) * NH + h) * DH * DH;
    float* Wo = We + (size_t)((kv * LAY + l) * 3 + e) * HID * HID;
    float* bo = be + (size_t)((kv * LAY + l) * 3 + e) * HID;

    __shared__ float sA[DH][DH];
    if (threadIdx.x < DH * DH / 2) {
        int d = threadIdx.x >> 4, c = (threadIdx.x & 15) * 2;
        sA[d][c]     = A[d * DH + c];
        sA[d][c + 1] = A[d * DH + c + 1];
        sA[d + 16][c]     = A[(d + 16) * DH + c];
        sA[d + 16][c + 1] = A[(d + 16) * DH + c + 1];
    }
    __syncthreads();

    int i = threadIdx.x;
    float w[DH];
#pragma unroll
    for (int d = 0; d < DH; d++) w[d] = W[(size_t)i * HID + h * DH + d];
#pragma unroll 4
    for (int c = 0; c < DH; c++) {
        float acc = 0.0f;
#pragma unroll
        for (int d = 0; d < DH; d++) acc += w[d] * sA[d][c];
        Wo[(size_t)i * HID + h * DH + c] = acc;
    }
    if (i < DH) {
        float acc = 0.0f;
#pragma unroll
        for (int d = 0; d < DH; d++) acc += b[h * DH + d] * sA[d][i];
        bo[h * DH + i] = acc;
    }
}

// ---------------------------------------------------------------------------
// Transpose + split fp32 weight [K][N] -> bf16 hi/lo [N][K] (W1 only)
// ---------------------------------------------------------------------------
__global__ __launch_bounds__(256)
void wsplit_k(const float* __restrict__ src, __nv_bfloat16* __restrict__ hi,
              __nv_bfloat16* __restrict__ lo, int K, int N)
{
    int i = blockIdx.x * 256 + threadIdx.x;
    if (i >= K * N) return;
    int n = i / K, k = i - n * K;
    float w = src[(size_t)k * N + n];
    __nv_bfloat16 h = __float2bfloat16(w);
    hi[i] = h;
    lo[i] = __float2bfloat16(w - __bfloat162float(h));
}

// ---------------------------------------------------------------------------
// Batched transpose+split for all K=256 weights: Wq(6) We(12) Wa(6) W2(1).
// ---------------------------------------------------------------------------
__global__ __launch_bounds__(256)
void wsplit_all(const float* __restrict__ Wq, const float* __restrict__ We,
                const float* __restrict__ Wa, const float* __restrict__ W2,
                __nv_bfloat16* __restrict__ bh, __nv_bfloat16* __restrict__ bl)
{
    int bid = blockIdx.x;
    const float* src;
    size_t off;
    int N, inner;
    if (bid < 6144) {
        int seg = bid >> 8;
        inner = ((bid & 255) << 8) | threadIdx.x;
        N = 256;
        if (seg < 6)       { src = Wq + (size_t)seg * 65536;        off = WB_WQ + (size_t)seg * 65536; }
        else if (seg < 18) { src = We + (size_t)(seg - 6) * 65536;  off = WB_WE + (size_t)(seg - 6) * 65536; }
        else               { src = Wa + (size_t)(seg - 18) * 65536; off = WB_WA + (size_t)(seg - 18) * 65536; }
    } else {
        inner = ((bid - 6144) << 8) | threadIdx.x;
        N = 128; src = W2; off = WB_W2;
    }
    int n = inner >> 8;
    int k = inner & 255;
    float w = src[(size_t)k * N + n];
    __nv_bfloat16 h = __float2bfloat16(w);
    bh[off + inner] = h;
    bl[off + inner] = __float2bfloat16(w - __bfloat162float(h));
}

#define LDS 40   // smem row stride in halves (80B: conflict-free ldmatrix)

// ---------------------------------------------------------------------------
// Proven convert-GEMM (mainloop structure verbatim R13-R16, 2 CTA/SM):
// AH: 0 = fp32 A, 1 = __half A.  NT: 3 = full split, 2 = drop Al*Bh.
// outmode: 0 = fp32 C, 1 = __half C, 2 = bf16 hi/lo pair (Ch, Cl)
// epi=2 reads skip input from bf16 pair (Xh, Xl).
// ---------------------------------------------------------------------------
template <int AH, int NT>
__global__ __launch_bounds__(256)
void gemm_mma(const void* __restrict__ Avoid,
              const __nv_bfloat16* __restrict__ Bh,
              const __nv_bfloat16* __restrict__ Bl,
              const float* __restrict__ bias,
              const __nv_bfloat16* __restrict__ Xh,
              const __nv_bfloat16* __restrict__ Xl,
              const float* __restrict__ skipp, float* __restrict__ C,
              __nv_bfloat16* __restrict__ Ch, __nv_bfloat16* __restrict__ Cl,
              int M, int N, int K, int actA, int epi, int outmode)
{
    __shared__ __align__(16) __nv_bfloat16 sAh[128 * LDS];
    __shared__ __align__(16) __nv_bfloat16 sAl[128 * LDS];
    __shared__ __align__(16) __nv_bfloat16 sBh[128 * LDS];
    __shared__ __align__(16) __nv_bfloat16 sBl[128 * LDS];

    const int tid  = threadIdx.x;
    const int wid  = tid >> 5;
    const int lane = tid & 31;
    const int wm   = wid >> 2;
    const int wn   = wid & 3;
    const int row0 = blockIdx.y * 128;
    const int col0 = blockIdx.x * 128;

    const int lrow = tid >> 1;
    const int lk   = (tid & 1) * 16;
    const int aGR  = row0 + lrow;
    const bool av  = (aGR < M);
    const __nv_bfloat16* BHrow = Bh + (size_t)(col0 + lrow) * K;
    const __nv_bfloat16* BLrow = Bl + (size_t)(col0 + lrow) * K;

    const int a_r = (lane & 7) + ((lane >> 3) & 1) * 8;
    const int a_c = ((lane >> 4) & 1) * 8;
    const int b_r = (lane & 7);
    const int b_c = ((lane >> 3) & 1) * 8;

    const uint32_t uAh = smem_u32(sAh), uAl = smem_u32(sAl);
    const uint32_t uBh = smem_u32(sBh), uBl = smem_u32(sBl);
    const uint32_t aoff = (uint32_t)((wm * 64 + a_r) * LDS + a_c) * 2;
    const uint32_t boff = (uint32_t)((wn * 32 + b_r) * LDS + b_c) * 2;
    const uint32_t sto  = (uint32_t)(lrow * LDS + lk);

    float acc[4][4][4];
#pragma unroll
    for (int i = 0; i < 4; i++)
#pragma unroll
        for (int j = 0; j < 4; j++)
#pragma unroll
            for (int r = 0; r < 4; r++) acc[i][j][r] = 0.0f;

    const int NC = K / 32;
    for (int c = 0; c < NC; c++) {
        const int kb = c * 32 + lk;

        float4 f0, f1, f2, f3;
        if (AH == 0) {
            const float* Arow = (const float*)Avoid + (size_t)aGR * K;
            if (av) {
                f0 = *(const float4*)(Arow + kb);
                f1 = *(const float4*)(Arow + kb + 4);
                f2 = *(const float4*)(Arow + kb + 8);
                f3 = *(const float4*)(Arow + kb + 12);
            } else {
                f0 = make_float4(0.f, 0.f, 0.f, 0.f); f1 = f0; f2 = f0; f3 = f0;
            }
        } else {
            const __half* Arow = (const __half*)Avoid + (size_t)aGR * K;
            uint4 p0, p1;
            if (av) {
                p0 = *(const uint4*)(Arow + kb);
                p1 = *(const uint4*)(Arow + kb + 8);
            } else {
                p0 = make_uint4(0u, 0u, 0u, 0u); p1 = p0;
            }
            const __half2* q = (const __half2*)&p0;
            float2 a0 = __half22float2(q[0]), a1 = __half22float2(q[1]);
            float2 a2 = __half22float2(q[2]), a3 = __half22float2(q[3]);
            const __half2* r = (const __half2*)&p1;
            float2 a4 = __half22float2(r[0]), a5 = __half22float2(r[1]);
            float2 a6 = __half22float2(r[2]), a7 = __half22float2(r[3]);
            f0 = make_float4(a0.x, a0.y, a1.x, a1.y);
            f1 = make_float4(a2.x, a2.y, a3.x, a3.y);
            f2 = make_float4(a4.x, a4.y, a5.x, a5.y);
            f3 = make_float4(a6.x, a6.y, a7.x, a7.y);
        }
        if (actA) {
            f0.x = geluf(f0.x); f0.y = geluf(f0.y); f0.z = geluf(f0.z); f0.w = geluf(f0.w);
            f1.x = geluf(f1.x); f1.y = geluf(f1.y); f1.z = geluf(f1.z); f1.w = geluf(f1.w);
            f2.x = geluf(f2.x); f2.y = geluf(f2.y); f2.z = geluf(f2.z); f2.w = geluf(f2.w);
            f3.x = geluf(f3.x); f3.y = geluf(f3.y); f3.z = geluf(f3.z); f3.w = geluf(f3.w);
        }
        uint4 bh0 = *(const uint4*)(BHrow + kb);
        uint4 bh1 = *(const uint4*)(BHrow + kb + 8);
        uint4 bl0 = *(const uint4*)(BLrow + kb);
        uint4 bl1 = *(const uint4*)(BLrow + kb + 8);

        if (c) __syncthreads();

        __nv_bfloat162 h0 = __floats2bfloat162_rn(f0.x, f0.y);
        __nv_bfloat162 h1 = __floats2bfloat162_rn(f0.z, f0.w);
        __nv_bfloat162 h2 = __floats2bfloat162_rn(f1.x, f1.y);
        __nv_bfloat162 h3 = __floats2bfloat162_rn(f1.z, f1.w);
        __nv_bfloat162 h4 = __floats2bfloat162_rn(f2.x, f2.y);
        __nv_bfloat162 h5 = __floats2bfloat162_rn(f2.z, f2.w);
        __nv_bfloat162 h6 = __floats2bfloat162_rn(f3.x, f3.y);
        __nv_bfloat162 h7 = __floats2bfloat162_rn(f3.z, f3.w);
        *(uint4*)&sAh[sto]     = make_uint4(*(uint32_t*)&h0, *(uint32_t*)&h1, *(uint32_t*)&h2, *(uint32_t*)&h3);
        *(uint4*)&sAh[sto + 8] = make_uint4(*(uint32_t*)&h4, *(uint32_t*)&h5, *(uint32_t*)&h6, *(uint32_t*)&h7);
        if (NT == 3) {
            __nv_bfloat162 l0 = __floats2bfloat162_rn(f0.x - __bfloat162float(h0.x), f0.y - __bfloat162float(h0.y));
            __nv_bfloat162 l1 = __floats2bfloat162_rn(f0.z - __bfloat162float(h1.x), f0.w - __bfloat162float(h1.y));
            __nv_bfloat162 l2 = __floats2bfloat162_rn(f1.x - __bfloat162float(h2.x), f1.y - __bfloat162float(h2.y));
            __nv_bfloat162 l3 = __floats2bfloat162_rn(f1.z - __bfloat162float(h3.x), f1.w - __bfloat162float(h3.y));
            __nv_bfloat162 l4 = __floats2bfloat162_rn(f2.x - __bfloat162float(h4.x), f2.y - __bfloat162float(h4.y));
            __nv_bfloat162 l5 = __floats2bfloat162_rn(f2.z - __bfloat162float(h5.x), f2.w - __bfloat162float(h5.y));
            __nv_bfloat162 l6 = __floats2bfloat162_rn(f3.x - __bfloat162float(h6.x), f3.y - __bfloat162float(h6.y));
            __nv_bfloat162 l7 = __floats2bfloat162_rn(f3.z - __bfloat162float(h7.x), f3.w - __bfloat162float(h7.y));
            *(uint4*)&sAl[sto]     = make_uint4(*(uint32_t*)&l0, *(uint32_t*)&l1, *(uint32_t*)&l2, *(uint32_t*)&l3);
            *(uint4*)&sAl[sto + 8] = make_uint4(*(uint32_t*)&l4, *(uint32_t*)&l5, *(uint32_t*)&l6, *(uint32_t*)&l7);
        }
        *(uint4*)&sBh[sto]     = bh0;
        *(uint4*)&sBh[sto + 8] = bh1;
        *(uint4*)&sBl[sto]     = bl0;
        *(uint4*)&sBl[sto + 8] = bl1;
        __syncthreads();

#pragma unroll
        for (int ks = 0; ks < 2; ks++) {
            const uint32_t kof = (uint32_t)(ks * 16) * 2;
            uint32_t ah[4][4], al[4][4];
#pragma unroll
            for (int i = 0; i < 4; i++) {
                uint32_t ro = (uint32_t)(i * 16 * LDS) * 2;
                ldm_x4(ah[i], uAh + aoff + ro + kof);
                if (NT == 3) ldm_x4(al[i], uAl + aoff + ro + kof);
            }
            uint32_t bhf[4][2], blf[4][2];
#pragma unroll
            for (int j = 0; j < 4; j++) {
                uint32_t ro = (uint32_t)(j * 8 * LDS) * 2;
                ldm_x2(bhf[j], uBh + boff + ro + kof);
                ldm_x2(blf[j], uBl + boff + ro + kof);
            }
#pragma unroll
            for (int i = 0; i < 4; i++)
#pragma unroll
                for (int j = 0; j < 4; j++) {
                    mma_bf16(acc[i][j], ah[i], bhf[j]);
                    mma_bf16(acc[i][j], ah[i], blf[j]);
                    if (NT == 3) mma_bf16(acc[i][j], al[i], bhf[j]);
                }
        }
    }

    float g = 0.0f;
    if (epi == 2) g = 1.0f / (1.0f + expf(-skipp[0]));

#pragma unroll
    for (int i = 0; i < 4; i++) {
#pragma unroll
        for (int half = 0; half < 2; half++) {
            int m = row0 + wm * 64 + i * 16 + (lane >> 2) + half * 8;
            if (m >= M) continue;
            size_t rb = (size_t)m * N;
#pragma unroll
            for (int j = 0; j < 4; j++) {
                int n = col0 + wn * 32 + j * 8 + (lane & 3) * 2;
                float v0 = acc[i][j][half * 2 + 0] + bias[n];
                float v1 = acc[i][j][half * 2 + 1] + bias[n + 1];
                if (epi == 1) {
                    v0 = (v0 > 0.f) ? v0 : 0.01f * v0;
                    v1 = (v1 > 0.f) ? v1 : 0.01f * v1;
                } else if (epi == 2) {
                    __nv_bfloat162 xh2 = *(const __nv_bfloat162*)(Xh + rb + n);
                    __nv_bfloat162 xl2 = *(const __nv_bfloat162*)(Xl + rb + n);
                    float x0 = __bfloat162float(xh2.x) + __bfloat162float(xl2.x);
                    float x1 = __bfloat162float(xh2.y) + __bfloat162float(xl2.y);
                    v0 = g * v0 + (1.f - g) * x0;
                    v1 = g * v1 + (1.f - g) * x1;
                }
                if (outmode == 2) {
                    __nv_bfloat16 ch0 = __float2bfloat16(v0);
                    __nv_bfloat16 ch1 = __float2bfloat16(v1);
                    __nv_bfloat162 co; co.x = ch0; co.y = ch1;
                    *(__nv_bfloat162*)(Ch + rb + n) = co;
                    __nv_bfloat162 cl;
                    cl.x = __float2bfloat16(v0 - __bfloat162float(ch0));
                    cl.y = __float2bfloat16(v1 - __bfloat162float(ch1));
                    *(__nv_bfloat162*)(Cl + rb + n) = cl;
                } else if (outmode == 1) {
                    *(__half2*)((__half*)C + rb + n) = __floats2half2_rn(v0, v1);
                } else {
                    float2 o; o.x = v0; o.y = v1;
                    *(float2*)(C + rb + n) = o;
                }
            }
        }
    }
}

// ---------------------------------------------------------------------------
// Async GEMM (templated on NTERMS): A pre-split bf16 hi/lo [M][256].
// 2-stage cp.async pipeline, K fixed at 256. Last-chunk wait0 (exact).
// NTERMS=3: Ah*Bh+Ah*Bl+Al*Bh. NTERMS=1: Ah*Bh only (skips Al/Bl loads too).
// ---------------------------------------------------------------------------
#define ATILE (128 * LDS)         // halves per tile (5120)
#define ASTG  (4 * ATILE)         // halves per stage (20480)
#define DSMEM_A (2 * ASTG * 2)    // bytes (81920)

template <int NTERMS>
__global__ __launch_bounds__(256)
void gemm_async(const __nv_bfloat16* __restrict__ Ah,
                const __nv_bfloat16* __restrict__ Al,
                const __nv_bfloat16* __restrict__ Bh,
                const __nv_bfloat16* __restrict__ Bl,
                const float* __restrict__ bias, float* __restrict__ C,
                int M, int N, int epi, int outmode)
{
    extern __shared__ __align__(16) __nv_bfloat16 sm[];
    const uint32_t smb = smem_u32(sm);

    const int tid  = threadIdx.x;
    const int wid  = tid >> 5;
    const int lane = tid & 31;
    const int wm   = wid >> 2;
    const int wn   = wid & 3;
    const int row0 = blockIdx.y * 128;
    const int col0 = blockIdx.x * 128;
    const int K = 256;

    const int a_r = (lane & 7) + ((lane >> 3) & 1) * 8;
    const int a_c = ((lane >> 4) & 1) * 8;
    const int b_r = (lane & 7);
    const int b_c = ((lane >> 3) & 1) * 8;
    const uint32_t aoff = (uint32_t)((wm * 64 + a_r) * LDS + a_c) * 2;
    const uint32_t boff = (uint32_t)((wn * 32 + b_r) * LDS + b_c) * 2;

    float acc[4][4][4];
#pragma unroll
    for (int i = 0; i < 4; i++)
#pragma unroll
        for (int j = 0; j < 4; j++)
#pragma unroll
            for (int r = 0; r < 4; r++) acc[i][j][r] = 0.0f;

    const int NC = 8;

    auto issue = [&](int stage, int chunk) {
        const int kb = chunk * 32;
#pragma unroll
        for (int i = 0; i < 2; i++) {
            int cid = tid + i * 256;
            int row = cid >> 2;
            int seg = cid & 3;
            uint32_t dst = smb + (uint32_t)(stage * ASTG + row * LDS + seg * 8) * 2;
            const int ga = row0 + row;
            uint32_t pa = (ga < M) ? 16u : 0u;
            const __nv_bfloat16* sa = Ah + (size_t)ga * K + kb + seg * 8;
            const __nv_bfloat16* sb = Bh + (size_t)(col0 + row) * K + kb + seg * 8;
            CP_ASYNC16P(dst,                 sa, pa);
            CP_ASYNC16P(dst + 2 * ATILE * 2, sb, 16u);
            if (NTERMS == 3) {
                const __nv_bfloat16* sl = Al + (size_t)ga * K + kb + seg * 8;
                const __nv_bfloat16* sc = Bl + (size_t)(col0 + row) * K + kb + seg * 8;
                CP_ASYNC16P(dst + ATILE * 2,     sl, pa);
                CP_ASYNC16P(dst + 3 * ATILE * 2, sc, 16u);
            }
        }
        CP_COMMIT();
    };

    issue(0, 0);
    issue(1, 1);

    for (int c = 0; c < NC; c++) {
        const int st = c & 1;
        if (c >= NC - 1) CP_WAIT0(); else CP_WAIT1();
        __syncthreads();

        const uint32_t base = smb + (uint32_t)(st * ASTG) * 2;
        const uint32_t uAh = base;
        const uint32_t uAl = base + ATILE * 2;
        const uint32_t uBh = base + 2 * ATILE * 2;
        const uint32_t uBl = base + 3 * ATILE * 2;
#pragma unroll
        for (int ks = 0; ks < 2; ks++) {
            const uint32_t kof = (uint32_t)(ks * 16) * 2;
            uint32_t ah[4][4], al[4][4];
#pragma unroll
            for (int i = 0; i < 4; i++) {
                uint32_t ro = (uint32_t)(i * 16 * LDS) * 2;
                ldm_x4(ah[i], uAh + aoff + ro + kof);
                if (NTERMS == 3) ldm_x4(al[i], uAl + aoff + ro + kof);
            }
            uint32_t bhf[4][2], blf[4][2];
#pragma unroll
            for (int j = 0; j < 4; j++) {
                uint32_t ro = (uint32_t)(j * 8 * LDS) * 2;
                ldm_x2(bhf[j], uBh + boff + ro + kof);
                if (NTERMS == 3) ldm_x2(blf[j], uBl + boff + ro + kof);
            }
#pragma unroll
            for (int i = 0; i < 4; i++)
#pragma unroll
                for (int j = 0; j < 4; j++) {
                    mma_bf16(acc[i][j], ah[i], bhf[j]);
                    if (NTERMS == 3) {
                        mma_bf16(acc[i][j], ah[i], blf[j]);
                        mma_bf16(acc[i][j], al[i], bhf[j]);
                    }
                }
        }
        __syncthreads();
        if (c + 2 < NC) issue(st, c + 2);
    }

    // ---- epilogue ----
#pragma unroll
    for (int i = 0; i < 4; i++) {
#pragma unroll
        for (int half = 0; half < 2; half++) {
            int m = row0 + wm * 64 + i * 16 + (lane >> 2) + half * 8;
            if (m >= M) continue;
            size_t rb = (size_t)m * N;
#pragma unroll
            for (int j = 0; j < 4; j++) {
                int n = col0 + wn * 32 + j * 8 + (lane & 3) * 2;
                float v0 = acc[i][j][half * 2 + 0] + bias[n];
                float v1 = acc[i][j][half * 2 + 1] + bias[n + 1];
                if (epi == 1) {
                    v0 = (v0 > 0.f) ? v0 : 0.01f * v0;
                    v1 = (v1 > 0.f) ? v1 : 0.01f * v1;
                }
                if (outmode == 1) {
                    *(__half2*)((__half*)C + rb + n) = __floats2half2_rn(v0, v1);
                } else {
                    float2 o; o.x = v0; o.y = v1;
                    *(float2*)(C + rb + n) = o;
                }
            }
        }
    }
}

// ---------------------------------------------------------------------------
// Fused edge logits + exp + denominator (fp16 KR/Q, verified R10-R16).
// ---------------------------------------------------------------------------
__global__ __launch_bounds__(256)
void logits_k(const __half* __restrict__ KR, const __half* __restrict__ Q,
              const int* __restrict__ src, const int* __restrict__ dst,
              const float* __restrict__ prel, float* __restrict__ expv,
              float* __restrict__ den, int E, int dst_off)
{
    int w    = (blockIdx.x * 256 + threadIdx.x) >> 5;
    int lane = threadIdx.x & 31;
    if (w >= E) return;
    int r = src[w], c = dst[w];
    const __half* kp = KR + (size_t)r * HID;
    const __half* qp = Q + (size_t)(dst_off + c) * HID;
    const float inv = 0.17677669529663687f;

    uint4 kv = *(const uint4*)(kp + lane * 8);
    uint4 qv = *(const uint4*)(qp + lane * 8);
    const __half2* k2 = (const __half2*)&kv;
    const __half2* q2 = (const __half2*)&qv;
    float v = 0.0f;
#pragma unroll
    for (int i = 0; i < 4; i++) {
        float2 a = __half22float2(k2[i]);
        float2 b = __half22float2(q2[i]);
        v += a.x * b.x + a.y * b.y;
    }
    v += __shfl_down_sync(0xffffffffu, v, 2);
    v += __shfl_down_sync(0xffffffffu, v, 1);
    if ((lane & 3) == 0) {
        int h = lane >> 2;
        float ex = expf(v * prel[h] * inv);
        expv[(size_t)w * NH + h] = ex;
        atomicAdd(&den[(size_t)c * NH + h], ex);
    }
}

// ---------------------------------------------------------------------------
// Message scatter (fp16 VR, fp16 OUT): out[dst, :] += vr[src, :] * attn.
// Warp per edge; lane covers 8 halves; single red.global.add.noftz.v4.f16x2.
// ---------------------------------------------------------------------------
__global__ __launch_bounds__(256)
void msg_k(const __half* __restrict__ VR, const int* __restrict__ src,
           const int* __restrict__ dst, const float* __restrict__ exv,
           const float* __restrict__ den, __half* __restrict__ out,
           int E, int dst_off)
{
    int eid = blockIdx.x * 8 + (threadIdx.x >> 5);
    if (eid >= E) return;
    int j = threadIdx.x & 31;          // covers halves [8j, 8j+8)
    int h = j >> 2;                    // 4 lanes per 32-wide head
    int r = src[eid], c = dst[eid];
    float attn = exv[(size_t)eid * NH + h] / (den[(size_t)c * NH + h] + 1e-16f);
    uint4 v = *(const uint4*)(VR + (size_t)r * HID + j * 8);
    __half2 a2 = __float2half2_rn(attn);
    __half2 m0 = __hmul2(((const __half2*)&v)[0], a2);
    __half2 m1 = __hmul2(((const __half2*)&v)[1], a2);
    __half2 m2 = __hmul2(((const __half2*)&v)[2], a2);
    __half2 m3 = __hmul2(((const __half2*)&v)[3], a2);
    __half* dp = out + (size_t)(dst_off + c) * HID + j * 8;
    asm volatile("red.global.add.noftz.v4.f16x2 [%0], {%1,%2,%3,%4};"
                 :: "l"(dp), "r"(*(uint32_t*)&m0), "r"(*(uint32_t*)&m1),
                    "r"(*(uint32_t*)&m2), "r"(*(uint32_t*)&m3)
                 : "memory");
}

// ---------------------------------------------------------------------------
// Host orchestration
// ---------------------------------------------------------------------------
extern "C" void kernel_launch(void* const* d_in, const int* in_sizes, int n_in,
                              void* d_out, int out_size)
{
    (void)n_in; (void)out_size;

    const float* xin[3] = { (const float*)d_in[0], (const float*)d_in[1],
                            (const float*)d_in[2] };
    const int* srcs[3] = { (const int*)d_in[3], (const int*)d_in[5], (const int*)d_in[7] };
    const int* dsts[3] = { (const int*)d_in[4], (const int*)d_in[6], (const int*)d_in[8] };
    int Es[3]   = { in_sizes[3], in_sizes[5], in_sizes[7] };
    int styp[3] = { 1, 0, 2 };
    int dtyp[3] = { 2, 2, 0 };

    int Nn[3] = { in_sizes[0] / INC, in_sizes[1] / INC, in_sizes[2] / INC };
    size_t off[3] = { 0, (size_t)Nn[0], (size_t)Nn[0] + (size_t)Nn[1] };
    size_t ntot = off[2] + (size_t)Nn[2];

    const float* W1    = (const float*)d_in[9];
    const float* b1    = (const float*)d_in[10];
    const float* W2    = (const float*)d_in[11];
    const float* b2    = (const float*)d_in[12];
    const float* Wk    = (const float*)d_in[13];
    const float* bk    = (const float*)d_in[14];
    const float* Wq    = (const float*)d_in[15];
    const float* bq    = (const float*)d_in[16];
    const float* Wv    = (const float*)d_in[17];
    const float* bv    = (const float*)d_in[18];
    const float* Wa    = (const float*)d_in[19];
    const float* ba    = (const float*)d_in[20];
    const float* skp   = (const float*)d_in[21];
    const float* a_rel = (const float*)d_in[22];
    const float* m_rel = (const float*)d_in[23];
    const float* p_rel = (const float*)d_in[24];

    float *xf, *x2f, *Qb, *ob, *kr, *vr, *lg, *dn, *We, *be;
    __nv_bfloat16 *bh, *bl;
    cudaGetSymbolAddress((void**)&xf,  g_x);
    cudaGetSymbolAddress((void**)&x2f, g_x2);
    cudaGetSymbolAddress((void**)&Qb, g_Q);
    cudaGetSymbolAddress((void**)&ob, g_o);
    cudaGetSymbolAddress((void**)&kr, g_kr);
    cudaGetSymbolAddress((void**)&vr, g_vr);
    cudaGetSymbolAddress((void**)&lg, g_lg);
    cudaGetSymbolAddress((void**)&dn, g_dn);
    cudaGetSymbolAddress((void**)&We, g_we);
    cudaGetSymbolAddress((void**)&be, g_be);
    cudaGetSymbolAddress((void**)&bh, g_bh);
    cudaGetSymbolAddress((void**)&bl, g_bl);

    __nv_bfloat16* xh = (__nv_bfloat16*)xf;   // activation hi
    __nv_bfloat16* xl = (__nv_bfloat16*)x2f;  // activation lo
    __half* obh = (__half*)ob;                // fp16 attention accumulator

    cudaFuncSetAttribute(gemm_async<3>,
                         cudaFuncAttributeMaxDynamicSharedMemorySize, DSMEM_A);
    cudaFuncSetAttribute(gemm_async<1>,
                         cudaFuncAttributeMaxDynamicSharedMemorySize, DSMEM_A);

    // ---- prep: fold relations, then transpose+split all weights -----------
    wtrans_k<<<2 * LAY * 3 * NH, 256>>>(Wk, bk, Wv, bv, a_rel, m_rel, We, be);
    wsplit_k<<<768, 256>>>(W1, bh + WB_W1, bl + WB_W1, 768, 256);
    wsplit_all<<<6272, 256>>>(Wq, We, Wa, W2, bh, bl);

    // ---- input MLP: pair = split(lrelu(x @ W1 + b1))  (full 3-term) -------
    for (int t = 0; t < 3; t++) {
        dim3 grid(HID / 128, (Nn[t] + 127) / 128);
        gemm_mma<0, 3><<<grid, 256>>>(xin[t], bh + WB_W1, bl + WB_W1, b1,
                                      nullptr, nullptr, nullptr, nullptr,
                                      xh + off[t] * HID, xl + off[t] * HID,
                                      Nn[t], HID, INC, 0, 1, 2);
    }

    for (int l = 0; l < 2; l++) {
        // ---- Q projections (async<1>; only dst types review/user) ---------
        for (int t = 0; t < 3; t++) {
            if (t == 1) continue;
            size_t wo = WB_WQ + (size_t)(l * 3 + t) * 65536;
            dim3 grid(HID / 128, (Nn[t] + 127) / 128);
            gemm_async<1><<<grid, 256, DSMEM_A>>>(
                xh + off[t] * HID, xl + off[t] * HID, bh + wo, bl + wo,
                bq + (size_t)(l * 3 + t) * HID,
                (float*)((__half*)Qb + off[t] * HID), Nn[t], HID, 0, 1);
        }

        // ---- per-edge-type attention + aggregation ------------------------
        cudaMemsetAsync(obh, 0, ntot * HID * sizeof(__half), 0);
        for (int e = 0; e < 3; e++) {
            int s = styp[e], t = dtyp[e];
            if (Es[e] <= 0) continue;

            size_t ik = WB_WE + (size_t)((0 * LAY + l) * 3 + e) * 65536;
            size_t iv = WB_WE + (size_t)((1 * LAY + l) * 3 + e) * 65536;
            size_t bik = (size_t)((0 * LAY + l) * 3 + e) * HID;
            size_t biv = (size_t)((1 * LAY + l) * 3 + e) * HID;
            dim3 grid(HID / 128, (Nn[s] + 127) / 128);
            gemm_async<1><<<grid, 256, DSMEM_A>>>(
                xh + off[s] * HID, xl + off[s] * HID, bh + ik, bl + ik,
                be + bik, kr, Nn[s], HID, 0, 1);
            gemm_async<1><<<grid, 256, DSMEM_A>>>(
                xh + off[s] * HID, xl + off[s] * HID, bh + iv, bl + iv,
                be + biv, vr, Nn[s], HID, 0, 1);

            cudaMemsetAsync(dn, 0, (size_t)Nn[t] * NH * sizeof(float), 0);

            logits_k<<<(Es[e] * 32 + 255) / 256, 256>>>(
                (const __half*)kr, (const __half*)Qb, srcs[e], dsts[e],
                p_rel + (size_t)(l * 3 + e) * NH, lg, dn, Es[e], (int)off[t]);
            msg_k<<<(Es[e] + 7) / 8, 256>>>((const __half*)vr, srcs[e], dsts[e],
                                            lg, dn, obh, Es[e], (int)off[t]);
        }

        // ---- output projection + gated skip (fp16 A, 2-term) --------------
        for (int t = 0; t < 3; t++) {
            size_t wo = WB_WA + (size_t)(l * 3 + t) * 65536;
            dim3 grid(HID / 128, (Nn[t] + 127) / 128);
            gemm_mma<1, 2><<<grid, 256>>>(obh + off[t] * HID, bh + wo, bl + wo,
                                          ba + (size_t)(l * 3 + t) * HID,
                                          xh + off[t] * HID, xl + off[t] * HID,
                                          skp + (l * 3 + t), nullptr,
                                          xh + off[t] * HID, xl + off[t] * HID,
                                          Nn[t], HID, HID, 1, 2, 2);
        }
    }

    // ---- final MLP (async<3>): lrelu(x @ W2 + b2), concatenated -----------
    float* outp = (float*)d_out;
    for (int t = 0; t < 3; t++) {
        dim3 grid(OUTC / 128, (Nn[t] + 127) / 128);
        gemm_async<3><<<grid, 256, DSMEM_A>>>(
            xh + off[t] * HID, xl + off[t] * HID, bh + WB_W2, bl + WB_W2,
            b2, outp + off[t] * OUTC, Nn[t], OUTC, 1, 0);
    }
}